// round 8
// baseline (speedup 1.0000x reference)
#include <cuda_runtime.h>
#include <cuda_bf16.h>
#include <cstdint>

#define HD 128
#define NT 256
#define MT 32

// byte offsets in the 1024-aligned dynamic smem region
#define OFF_AVH 0u
#define OFF_AVM 8192u
#define OFF_AVL 16384u
#define OFF_ADH 24576u
#define OFF_ADL 32768u
#define OFF_BH  40960u
#define OFF_BM  57344u
#define OFF_BL  73728u
#define OFF_MISC 90112u
#define MAIN_SMEM (90112 + 4864 + 1024)

__device__ float2 g_head[3][2];
// pre-split swizzled weight tiles: [branch][layer(0=W2,1=W3)][3 split levels * 8192 u32]
__device__ uint32_t g_Bsplit[3][2][3 * 8192];

// ---------------------------------------------------------------------------
// bf16 split helpers (round-to-nearest splits)
// ---------------------------------------------------------------------------
__device__ __forceinline__ float bf_rn(float x, uint32_t& bits) {
    __nv_bfloat16 b = __float2bfloat16(x);
    bits = (uint32_t)__bfloat16_as_ushort(b);
    return __bfloat162float(b);
}
__device__ __forceinline__ void split3_pair(float a, float b,
                                            uint32_t& h, uint32_t& m, uint32_t& l) {
    uint32_t ha, ma, la, hb, mb, lb;
    float f = bf_rn(a, ha); float r1 = a - f;
    f = bf_rn(r1, ma);      float r2 = r1 - f;
    bf_rn(r2, la);
    f = bf_rn(b, hb);       r1 = b - f;
    f = bf_rn(r1, mb);      r2 = r1 - f;
    bf_rn(r2, lb);
    h = ha | (hb << 16); m = ma | (mb << 16); l = la | (lb << 16);
}
__device__ __forceinline__ void split2_pair(float a, float b,
                                            uint32_t& h, uint32_t& l) {
    uint32_t ha, la, hb, lb;
    float f = bf_rn(a, ha); bf_rn(a - f, la);
    f = bf_rn(b, hb);       bf_rn(b - f, lb);
    h = ha | (hb << 16); l = la | (lb << 16);
}

// swizzled byte offset inside a [rows x 128 bf16] tile (row stride 256B)
__device__ __forceinline__ uint32_t swz8(int row, int col8) {
    return (uint32_t)(row * 256) + ((uint32_t)((col8 ^ (row & 7))) << 4);
}

// ---------------------------------------------------------------------------
// ldmatrix / mma wrappers (baseline PTX, compute_103-safe)
// ---------------------------------------------------------------------------
__device__ __forceinline__ void ldmA(uint32_t f[4], uint32_t base, int r0, int ch, int lane) {
    int g = lane >> 3, i = lane & 7;
    int row = r0 + i + ((g & 1) << 3);
    int c   = ch + (g >> 1);
    uint32_t addr = base + swz8(row, c);
    asm volatile("ldmatrix.sync.aligned.m8n8.x4.shared.b16 {%0,%1,%2,%3}, [%4];"
                 : "=r"(f[0]), "=r"(f[1]), "=r"(f[2]), "=r"(f[3]) : "r"(addr));
}
__device__ __forceinline__ void ldmB(uint32_t f[4], uint32_t base, int n0, int ch, int lane) {
    int g = lane >> 3, i = lane & 7;
    int row = n0 + i + ((g >> 1) << 3);
    int c   = ch + (g & 1);
    uint32_t addr = base + swz8(row, c);
    asm volatile("ldmatrix.sync.aligned.m8n8.x4.shared.b16 {%0,%1,%2,%3}, [%4];"
                 : "=r"(f[0]), "=r"(f[1]), "=r"(f[2]), "=r"(f[3]) : "r"(addr));
}
__device__ __forceinline__ void mma16816(float c[4], const uint32_t a[4],
                                         uint32_t b0, uint32_t b1) {
    asm volatile("mma.sync.aligned.m16n8k16.row.col.f32.bf16.bf16.f32 "
                 "{%0,%1,%2,%3}, {%4,%5,%6,%7}, {%8,%9}, {%0,%1,%2,%3};"
                 : "+f"(c[0]), "+f"(c[1]), "+f"(c[2]), "+f"(c[3])
                 : "r"(a[0]), "r"(a[1]), "r"(a[2]), "r"(a[3]), "r"(b0), "r"(b1));
}

// copy one 64-col half of the three pre-split W tiles (48KB) GMEM -> SMEM
__device__ __forceinline__ void copy_Bhalf(const uint4* __restrict__ src,
                                           char* __restrict__ smA, int tid, int half) {
    #pragma unroll
    for (int s = 0; s < 3; ++s) {
        const uint4* sp = src + s * 2048 + half * 1024;
        uint4* dp = (uint4*)(smA + OFF_BH + s * 16384);
        #pragma unroll
        for (int i = 0; i < 4; ++i)
            dp[tid + i * NT] = sp[tid + i * NT];
    }
}

// one half's MMA: 8 ks, reads A tiles (32x128) + staged B half (64x128)
__device__ __forceinline__ void mma_half(uint32_t AVH, uint32_t AVM, uint32_t AVL,
                                         uint32_t ADH, uint32_t ADL,
                                         uint32_t BH, uint32_t BM, uint32_t BL,
                                         int m0, int n0, int lane,
                                         float accv1[2][4], float accv2[2][4],
                                         float accd[2][4])
{
    #pragma unroll
    for (int nt = 0; nt < 2; ++nt)
        #pragma unroll
        for (int q = 0; q < 4; ++q) { accv1[nt][q]=0.f; accv2[nt][q]=0.f; accd[nt][q]=0.f; }
    #pragma unroll
    for (int ks = 0; ks < 8; ++ks) {
        const int ch = ks * 2;
        uint32_t avh[4], avm[4], avl[4], adh[4], adl[4];
        uint32_t bh[4], bm[4], bl[4];
        ldmA(avh, AVH, m0, ch, lane);
        ldmA(avm, AVM, m0, ch, lane);
        ldmA(avl, AVL, m0, ch, lane);
        ldmA(adh, ADH, m0, ch, lane);
        ldmA(adl, ADL, m0, ch, lane);
        ldmB(bh, BH, n0, ch, lane);
        ldmB(bm, BM, n0, ch, lane);
        ldmB(bl, BL, n0, ch, lane);
        #pragma unroll
        for (int nt = 0; nt < 2; ++nt) {
            uint32_t b0h = bh[nt*2], b1h = bh[nt*2+1];
            uint32_t b0m = bm[nt*2], b1m = bm[nt*2+1];
            uint32_t b0l = bl[nt*2], b1l = bl[nt*2+1];
            mma16816(accv1[nt], avh, b0h, b1h);
            mma16816(accd[nt],  adh, b0h, b1h);
            mma16816(accv2[nt], avm, b0h, b1h);
            mma16816(accd[nt],  adl, b0h, b1h);
            mma16816(accv2[nt], avl, b0h, b1h);
            mma16816(accd[nt],  adh, b0m, b1m);
            mma16816(accv2[nt], avh, b0m, b1m);
            mma16816(accv2[nt], avm, b0m, b1m);
            mma16816(accv2[nt], avl, b0m, b1m);
            mma16816(accv2[nt], avh, b0l, b1l);
            mma16816(accv2[nt], avm, b0l, b1l);
        }
    }
}

// ---------------------------------------------------------------------------
// Prep kernel: split W2/W3 of every branch into swizzled bf16 H/M/L tiles
// ---------------------------------------------------------------------------
__global__ void prep_kernel(const float* __restrict__ W2,
                            const float* __restrict__ W3)
{
    int b = blockIdx.x >> 1, l = blockIdx.x & 1;
    const float* W = (l ? W3 : W2) + b * HD * HD;
    char* dst = (char*)g_Bsplit[b][l];
    for (int g = threadIdx.x; g < 2048; g += blockDim.x) {
        int j = g >> 4;
        int kg = (g & 15) * 8;
        float4 w0 = *(const float4*)(W + j * HD + kg);
        float4 w1 = *(const float4*)(W + j * HD + kg + 4);
        uint4 h, m, lo;
        split3_pair(w0.x, w0.y, h.x, m.x, lo.x);
        split3_pair(w0.z, w0.w, h.y, m.y, lo.y);
        split3_pair(w1.x, w1.y, h.z, m.z, lo.z);
        split3_pair(w1.z, w1.w, h.w, m.w, lo.w);
        uint32_t ao = swz8(j, kg >> 3);
        *(uint4*)(dst + ao)         = h;
        *(uint4*)(dst + 32768 + ao) = m;
        *(uint4*)(dst + 65536 + ao) = lo;
    }
}

// ---------------------------------------------------------------------------
// Head kernel (known-good fp32): (v, dv) at n=0,1 for all branches
// ---------------------------------------------------------------------------
#define HWS 129
__global__ void head_kernel(const float* __restrict__ t,
    const float* __restrict__ W1, const float* __restrict__ b1,
    const float* __restrict__ W2, const float* __restrict__ b2,
    const float* __restrict__ W3, const float* __restrict__ b3,
    const float* __restrict__ W4, const float* __restrict__ b4)
{
    extern __shared__ float hsm[];
    __shared__ float2 A[HD], B[HD];
    __shared__ float2 red[HD];
    const int j = threadIdx.x;
    float tv0 = t[0], tv1 = t[1];

    for (int b = 0; b < 3; ++b) {
        float w1 = W1[b*HD + j];
        float c1 = b1[b*HD + j];
        float c2 = b2[b*HD + j];
        float c3 = b3[b*HD + j];
        float w4 = W4[b*HD + j];
        for (int n = 0; n < 2; ++n) {
            float tn = (n == 0) ? tv0 : tv1;
            float pre = fmaf(tn, w1, c1);
            A[j] = make_float2(fmaxf(pre, 0.f), pre > 0.f ? w1 : 0.f);
            __syncthreads();
            for (int idx = j; idx < HD*HD; idx += HD) {
                int jj = idx >> 7, k = idx & 127;
                hsm[jj*HWS + k] = W2[b*HD*HD + idx];
            }
            __syncthreads();
            {
                float av = 0.f, ad = 0.f;
                #pragma unroll 8
                for (int k = 0; k < HD; ++k) {
                    float w = hsm[j*HWS + k]; float2 h = A[k];
                    av = fmaf(w, h.x, av); ad = fmaf(w, h.y, ad);
                }
                float p = av + c2;
                B[j] = make_float2(fmaxf(p, 0.f), p > 0.f ? ad : 0.f);
            }
            __syncthreads();
            for (int idx = j; idx < HD*HD; idx += HD) {
                int jj = idx >> 7, k = idx & 127;
                hsm[jj*HWS + k] = W3[b*HD*HD + idx];
            }
            __syncthreads();
            {
                float av = 0.f, ad = 0.f;
                #pragma unroll 8
                for (int k = 0; k < HD; ++k) {
                    float w = hsm[j*HWS + k]; float2 h = B[k];
                    av = fmaf(w, h.x, av); ad = fmaf(w, h.y, ad);
                }
                float p = av + c3;
                A[j] = make_float2(fmaxf(p, 0.f), p > 0.f ? ad : 0.f);
            }
            __syncthreads();
            red[j] = make_float2(w4 * A[j].x, w4 * A[j].y);
            __syncthreads();
            for (int s = 64; s > 0; s >>= 1) {
                if (j < s) { red[j].x += red[j+s].x; red[j].y += red[j+s].y; }
                __syncthreads();
            }
            if (j == 0) g_head[b][n] = make_float2(red[0].x + b4[b], red[0].y);
            __syncthreads();
        }
    }
}

// ---------------------------------------------------------------------------
// Main kernel: 32 samples/CTA, 2 CTAs/SM, B staged in 64-col halves.
// Numerics identical to the 11-pass bf16 split scheme.
// ---------------------------------------------------------------------------
__global__ __launch_bounds__(NT, 2)
void main_kernel(const float* __restrict__ t,
    const float* __restrict__ W1, const float* __restrict__ b1,
    const float* __restrict__ b2, const float* __restrict__ b3,
    const float* __restrict__ W4, const float* __restrict__ b4,
    float* __restrict__ out, int N)
{
    extern __shared__ char smem_raw[];
    const uint32_t sb_raw = (uint32_t)__cvta_generic_to_shared(smem_raw);
    const uint32_t sb = (sb_raw + 1023u) & ~1023u;
    char* smA = smem_raw + (sb - sb_raw);

    const int tid  = threadIdx.x;
    const int lane = tid & 31;
    const int w    = tid >> 5;          // 0..7
    const int m0   = (w >> 2) * 16;     // row slab (M=32)
    const int wn   = w & 3;
    const int n0   = wn * 16;           // col slab within the 64-col half

    float*  sW1 = (float*)(smA + OFF_MISC) + 0;
    float*  sC1 = (float*)(smA + OFF_MISC) + 128;
    float*  sB2 = (float*)(smA + OFF_MISC) + 256;
    float*  sB3 = (float*)(smA + OFF_MISC) + 384;
    float*  sW4 = (float*)(smA + OFF_MISC) + 512;
    float*  sT  = (float*)(smA + OFF_MISC) + 640;     // 32 floats
    float2* red = (float2*)(smA + OFF_MISC + 2816);   // [32][4]

    const int base = blockIdx.x * MT;
    if (tid < MT) sT[tid] = t[base + tid];

    const uint32_t AVH = sb + OFF_AVH, AVM = sb + OFF_AVM, AVL = sb + OFF_AVL;
    const uint32_t ADH = sb + OFF_ADH, ADL = sb + OFF_ADL;
    const uint32_t BH  = sb + OFF_BH,  BM  = sb + OFF_BM,  BL  = sb + OFF_BL;

    for (int b = 0; b < 3; ++b) {
        if (tid < HD) {
            sW1[tid] = W1[b*HD + tid];
            sC1[tid] = b1[b*HD + tid];
            sB2[tid] = b2[b*HD + tid];
            sB3[tid] = b3[b*HD + tid];
            sW4[tid] = W4[b*HD + tid];
        }
        copy_Bhalf((const uint4*)g_Bsplit[b][0], smA, tid, 0);
        __syncthreads();

        // ---- layer 1: elementwise -> A split buffers (32 rows) ----
        #pragma unroll
        for (int i = 0; i < 2; ++i) {
            int g = tid + i * NT;          // 0..511
            int r = g >> 4, c0 = (g & 15) * 8;
            float tv = sT[r];
            float hv[8], hd[8];
            #pragma unroll
            for (int q = 0; q < 8; ++q) {
                float wv  = sW1[c0 + q];
                float pre = fmaf(tv, wv, sC1[c0 + q]);
                bool mk = pre > 0.f;
                hv[q] = mk ? pre : 0.f;
                hd[q] = mk ? wv  : 0.f;
            }
            uint4 vh, vm, vl, dh, dl;
            split3_pair(hv[0], hv[1], vh.x, vm.x, vl.x);
            split3_pair(hv[2], hv[3], vh.y, vm.y, vl.y);
            split3_pair(hv[4], hv[5], vh.z, vm.z, vl.z);
            split3_pair(hv[6], hv[7], vh.w, vm.w, vl.w);
            split2_pair(hd[0], hd[1], dh.x, dl.x);
            split2_pair(hd[2], hd[3], dh.y, dl.y);
            split2_pair(hd[4], hd[5], dh.z, dl.z);
            split2_pair(hd[6], hd[7], dh.w, dl.w);
            uint32_t ao = swz8(r, c0 >> 3);
            *(uint4*)(smA + OFF_AVH + ao) = vh;
            *(uint4*)(smA + OFF_AVM + ao) = vm;
            *(uint4*)(smA + OFF_AVL + ao) = vl;
            *(uint4*)(smA + OFF_ADH + ao) = dh;
            *(uint4*)(smA + OFF_ADL + ao) = dl;
        }
        __syncthreads();

        #pragma unroll 1
        for (int layer = 0; layer < 2; ++layer) {
            const uint4* bsrc = (const uint4*)g_Bsplit[b][layer];
            if (layer == 1) {               // layer 0's half0 B staged above
                copy_Bhalf(bsrc, smA, tid, 0);
                __syncthreads();
            }

            float accv1[2][4], accv2[2][4], accd[2][4];
            float hval[2][8], hder[2][8];   // per-half epilogue results (layer 0)
            float sv[2] = {0.f, 0.f}, sd[2] = {0.f, 0.f};  // layer 1 dots

            #pragma unroll
            for (int half = 0; half < 2; ++half) {
                if (half == 1) {
                    __syncthreads();        // everyone done reading B half0
                    copy_Bhalf(bsrc, smA, tid, 1);
                    __syncthreads();
                }
                mma_half(AVH, AVM, AVL, ADH, ADL, BH, BM, BL,
                         m0, n0, lane, accv1, accv2, accd);

                if (layer == 0) {
                    #pragma unroll
                    for (int nt = 0; nt < 2; ++nt) {
                        int c = half*64 + n0 + 8*nt + (lane & 3)*2;
                        float bb0 = sB2[c], bb1 = sB2[c+1];
                        #pragma unroll
                        for (int h = 0; h < 2; ++h) {
                            float p0 = accv1[nt][2*h]   + (accv2[nt][2*h]   + bb0);
                            float p1 = accv1[nt][2*h+1] + (accv2[nt][2*h+1] + bb1);
                            bool q0 = p0 > 0.f, q1 = p1 > 0.f;
                            int idx = nt*4 + h*2;
                            hval[half][idx]   = q0 ? p0 : 0.f;
                            hval[half][idx+1] = q1 ? p1 : 0.f;
                            hder[half][idx]   = q0 ? accd[nt][2*h]   : 0.f;
                            hder[half][idx+1] = q1 ? accd[nt][2*h+1] : 0.f;
                        }
                    }
                } else {
                    #pragma unroll
                    for (int nt = 0; nt < 2; ++nt) {
                        int c = half*64 + n0 + 8*nt + (lane & 3)*2;
                        float bb0 = sB3[c], bb1 = sB3[c+1];
                        float ww0 = sW4[c], ww1 = sW4[c+1];
                        #pragma unroll
                        for (int h = 0; h < 2; ++h) {
                            float p0 = accv1[nt][2*h]   + (accv2[nt][2*h]   + bb0);
                            float p1 = accv1[nt][2*h+1] + (accv2[nt][2*h+1] + bb1);
                            bool q0 = p0 > 0.f, q1 = p1 > 0.f;
                            sv[h] = fmaf(q0 ? p0 : 0.f, ww0, sv[h]);
                            sv[h] = fmaf(q1 ? p1 : 0.f, ww1, sv[h]);
                            sd[h] = fmaf(q0 ? accd[nt][2*h]   : 0.f, ww0, sd[h]);
                            sd[h] = fmaf(q1 ? accd[nt][2*h+1] : 0.f, ww1, sd[h]);
                        }
                    }
                }
            }
            __syncthreads();   // all warps done reading A (both halves) + B half1

            if (layer == 0) {
                // write new activations (both halves) into A buffers
                #pragma unroll
                for (int half = 0; half < 2; ++half)
                    #pragma unroll
                    for (int nt = 0; nt < 2; ++nt)
                        #pragma unroll
                        for (int h = 0; h < 2; ++h) {
                            int row = m0 + 8*h + (lane >> 2);
                            int c = half*64 + n0 + 8*nt + (lane & 3)*2;
                            int idx = nt*4 + h*2;
                            uint32_t vh, vm, vl, dh, dl;
                            split3_pair(hval[half][idx], hval[half][idx+1], vh, vm, vl);
                            split2_pair(hder[half][idx], hder[half][idx+1], dh, dl);
                            uint32_t ao = swz8(row, c >> 3) + ((c & 7) << 1);
                            *(uint32_t*)(smA + OFF_AVH + ao) = vh;
                            *(uint32_t*)(smA + OFF_AVM + ao) = vm;
                            *(uint32_t*)(smA + OFF_AVL + ao) = vl;
                            *(uint32_t*)(smA + OFF_ADH + ao) = dh;
                            *(uint32_t*)(smA + OFF_ADL + ao) = dl;
                        }
                __syncthreads();
            } else {
                // reduce per-row dots across the 4 n-warps
                #pragma unroll
                for (int h = 0; h < 2; ++h) {
                    float v = sv[h], d = sd[h];
                    v += __shfl_xor_sync(0xffffffffu, v, 1);
                    v += __shfl_xor_sync(0xffffffffu, v, 2);
                    d += __shfl_xor_sync(0xffffffffu, d, 1);
                    d += __shfl_xor_sync(0xffffffffu, d, 2);
                    if ((lane & 3) == 0) {
                        int row = m0 + 8*h + (lane >> 2);
                        red[row*4 + wn] = make_float2(v, d);
                    }
                }
                __syncthreads();

                if (tid < MT) {
                    float2 r0 = red[tid*4+0], r1 = red[tid*4+1],
                           r2 = red[tid*4+2], r3 = red[tid*4+3];
                    float v  = r0.x + r1.x + r2.x + r3.x + b4[b];
                    float dv = r0.y + r1.y + r2.y + r3.y;
                    float2 h0 = g_head[b][0];
                    float2 h1 = g_head[b][1];
                    float s = (b == 1) ? -1.f : 1.f;
                    float d1 = h1.x - h0.x;
                    float sg1 = (d1 > 0.f) ? 1.f : ((d1 < 0.f) ? -1.f : 0.f);
                    float dsign1 = s * sg1 * h1.y;
                    int n = base + tid;
                    float d = v - h0.x;
                    float vv, ds;
                    if (n == 0) {
                        vv = 0.f;
                        ds = (dsign1 >= 0.f) ? fabsf(dv) : -fabsf(dv);
                    } else {
                        float sg = (d > 0.f) ? 1.f : ((d < 0.f) ? -1.f : 0.f);
                        vv = s * fabsf(d);
                        ds = s * sg * dv;
                    }
                    out[b*N + n]       = vv;
                    out[(3 + b)*N + n] = ds;
                }
                __syncthreads();
            }
        }
    }
}

// ---------------------------------------------------------------------------
extern "C" void kernel_launch(void* const* d_in, const int* in_sizes, int n_in,
                              void* d_out, int out_size)
{
    const float* t  = (const float*)d_in[0];
    const float* W1 = (const float*)d_in[1];
    const float* b1 = (const float*)d_in[2];
    const float* W2 = (const float*)d_in[3];
    const float* b2 = (const float*)d_in[4];
    const float* W3 = (const float*)d_in[5];
    const float* b3 = (const float*)d_in[6];
    const float* W4 = (const float*)d_in[7];
    const float* b4 = (const float*)d_in[8];
    float* out = (float*)d_out;
    const int N = in_sizes[0];

    const int HEAD_SMEM = HD * HWS * 4;

    cudaFuncSetAttribute(main_kernel, cudaFuncAttributeMaxDynamicSharedMemorySize, MAIN_SMEM);
    cudaFuncSetAttribute(head_kernel, cudaFuncAttributeMaxDynamicSharedMemorySize, HEAD_SMEM);

    prep_kernel<<<6, NT>>>(W2, W3);
    head_kernel<<<1, HD, HEAD_SMEM>>>(t, W1, b1, W2, b2, W3, b3, W4, b4);
    main_kernel<<<N / MT, NT, MAIN_SMEM>>>(t, W1, b1, b2, b3, W4, b4, out, N);
}

// round 9
// speedup vs baseline: 1.1685x; 1.1685x over previous
#include <cuda_runtime.h>
#include <cuda_fp16.h>
#include <cstdint>

#define HD 128
#define NT 512
#define MT 64

// byte offsets in the 1024-aligned dynamic smem region
#define OFF_AVH 0u
#define OFF_AVM 16384u
#define OFF_AVL 32768u
#define OFF_ADH 49152u
#define OFF_ADL 65536u
#define OFF_BH  81920u
#define OFF_BM  114688u
#define OFF_BL  147456u
#define OFF_MISC 180224u
#define MAIN_SMEM (180224 + 8192 + 1024)

#define S_UP   2048.0f                  // 2^11
#define S_DN   4.8828125e-4f            // 2^-11
#define S_DN2  2.384185791015625e-7f    // 2^-22

__device__ float2 g_head[3][2];
// pre-split swizzled weight tiles per iteration (iter = 2*branch + layer):
// levels H/M/L each 8192 u32 (32KB)
__device__ uint32_t g_Bsplit[6][3 * 8192];

// ---------------------------------------------------------------------------
// scaled fp16 split helpers
// ---------------------------------------------------------------------------
__device__ __forceinline__ float f16_rn(float x, uint32_t& bits) {
    __half h = __float2half_rn(x);
    bits = (uint32_t)__half_as_ushort(h);
    return __half2float(h);
}
// x ≈ h + m*2^-11 + l*2^-22 ; all three stored values normal-range
__device__ __forceinline__ void split3f_pair(float a, float b,
                                             uint32_t& h, uint32_t& m, uint32_t& l) {
    uint32_t ha, ma, la, hb, mb, lb;
    float f = f16_rn(a, ha); float r = (a - f) * S_UP;
    f = f16_rn(r, ma);       float r2 = (r - f) * S_UP;
    f16_rn(r2, la);
    f = f16_rn(b, hb);       r = (b - f) * S_UP;
    f = f16_rn(r, mb);       r2 = (r - f) * S_UP;
    f16_rn(r2, lb);
    h = ha | (hb << 16); m = ma | (mb << 16); l = la | (lb << 16);
}
// x ≈ h + l*2^-11
__device__ __forceinline__ void split2f_pair(float a, float b,
                                             uint32_t& h, uint32_t& l) {
    uint32_t ha, la, hb, lb;
    float f = f16_rn(a, ha); f16_rn((a - f) * S_UP, la);
    f = f16_rn(b, hb);       f16_rn((b - f) * S_UP, lb);
    h = ha | (hb << 16); l = la | (lb << 16);
}

// swizzled byte offset inside a [rows x 128 f16] tile (row stride 256B)
__device__ __forceinline__ uint32_t swz8(int row, int col8) {
    return (uint32_t)(row * 256) + ((uint32_t)((col8 ^ (row & 7))) << 4);
}

// ---------------------------------------------------------------------------
// ldmatrix / mma wrappers (baseline PTX, compute_103-safe)
// ---------------------------------------------------------------------------
__device__ __forceinline__ void ldmA(uint32_t f[4], uint32_t base, int r0, int ch, int lane) {
    int g = lane >> 3, i = lane & 7;
    int row = r0 + i + ((g & 1) << 3);
    int c   = ch + (g >> 1);
    uint32_t addr = base + swz8(row, c);
    asm volatile("ldmatrix.sync.aligned.m8n8.x4.shared.b16 {%0,%1,%2,%3}, [%4];"
                 : "=r"(f[0]), "=r"(f[1]), "=r"(f[2]), "=r"(f[3]) : "r"(addr));
}
__device__ __forceinline__ void ldmB(uint32_t f[4], uint32_t base, int n0, int ch, int lane) {
    int g = lane >> 3, i = lane & 7;
    int row = n0 + i + ((g >> 1) << 3);
    int c   = ch + (g & 1);
    uint32_t addr = base + swz8(row, c);
    asm volatile("ldmatrix.sync.aligned.m8n8.x4.shared.b16 {%0,%1,%2,%3}, [%4];"
                 : "=r"(f[0]), "=r"(f[1]), "=r"(f[2]), "=r"(f[3]) : "r"(addr));
}
__device__ __forceinline__ void mma_f16(float c[4], const uint32_t a[4],
                                        uint32_t b0, uint32_t b1) {
    asm volatile("mma.sync.aligned.m16n8k16.row.col.f32.f16.f16.f32 "
                 "{%0,%1,%2,%3}, {%4,%5,%6,%7}, {%8,%9}, {%0,%1,%2,%3};"
                 : "+f"(c[0]), "+f"(c[1]), "+f"(c[2]), "+f"(c[3])
                 : "r"(a[0]), "r"(a[1]), "r"(a[2]), "r"(a[3]), "r"(b0), "r"(b1));
}

// cp.async one 32KB level (2048 uint4) GMEM -> SMEM, 4 x 16B per thread
__device__ __forceinline__ void prefetch_level(const uint4* __restrict__ src,
                                               uint32_t dst, int tid) {
    #pragma unroll
    for (int i = 0; i < 4; ++i) {
        uint32_t d = dst + (uint32_t)(tid + i * NT) * 16u;
        const uint4* s = src + tid + i * NT;
        asm volatile("cp.async.cg.shared.global [%0], [%1], 16;"
                     :: "r"(d), "l"(s) : "memory");
    }
    asm volatile("cp.async.commit_group;" ::: "memory");
}
#define CP_WAIT0() asm volatile("cp.async.wait_group 0;" ::: "memory")

// ---------------------------------------------------------------------------
// Prep kernel: split W2/W3 of every branch into swizzled scaled-fp16 tiles
// ---------------------------------------------------------------------------
__global__ void prep_kernel(const float* __restrict__ W2,
                            const float* __restrict__ W3)
{
    int iter = blockIdx.x;          // 0..5
    int b = iter >> 1, l = iter & 1;
    const float* W = (l ? W3 : W2) + b * HD * HD;
    char* dst = (char*)g_Bsplit[iter];
    for (int g = threadIdx.x; g < 2048; g += blockDim.x) {
        int j = g >> 4;
        int kg = (g & 15) * 8;
        float4 w0 = *(const float4*)(W + j * HD + kg);
        float4 w1 = *(const float4*)(W + j * HD + kg + 4);
        uint4 h, m, lo;
        split3f_pair(w0.x, w0.y, h.x, m.x, lo.x);
        split3f_pair(w0.z, w0.w, h.y, m.y, lo.y);
        split3f_pair(w1.x, w1.y, h.z, m.z, lo.z);
        split3f_pair(w1.z, w1.w, h.w, m.w, lo.w);
        uint32_t ao = swz8(j, kg >> 3);
        *(uint4*)(dst + ao)         = h;
        *(uint4*)(dst + 32768 + ao) = m;
        *(uint4*)(dst + 65536 + ao) = lo;
    }
}

// ---------------------------------------------------------------------------
// Head kernel (known-good fp32): (v, dv) at n=0,1 for all branches
// ---------------------------------------------------------------------------
#define HWS 129
__global__ void head_kernel(const float* __restrict__ t,
    const float* __restrict__ W1, const float* __restrict__ b1,
    const float* __restrict__ W2, const float* __restrict__ b2,
    const float* __restrict__ W3, const float* __restrict__ b3,
    const float* __restrict__ W4, const float* __restrict__ b4)
{
    extern __shared__ float hsm[];
    __shared__ float2 A[HD], B[HD];
    __shared__ float2 red[HD];
    const int j = threadIdx.x;
    float tv0 = t[0], tv1 = t[1];

    for (int b = 0; b < 3; ++b) {
        float w1 = W1[b*HD + j];
        float c1 = b1[b*HD + j];
        float c2 = b2[b*HD + j];
        float c3 = b3[b*HD + j];
        float w4 = W4[b*HD + j];
        for (int n = 0; n < 2; ++n) {
            float tn = (n == 0) ? tv0 : tv1;
            float pre = fmaf(tn, w1, c1);
            A[j] = make_float2(fmaxf(pre, 0.f), pre > 0.f ? w1 : 0.f);
            __syncthreads();
            for (int idx = j; idx < HD*HD; idx += HD) {
                int jj = idx >> 7, k = idx & 127;
                hsm[jj*HWS + k] = W2[b*HD*HD + idx];
            }
            __syncthreads();
            {
                float av = 0.f, ad = 0.f;
                #pragma unroll 8
                for (int k = 0; k < HD; ++k) {
                    float w = hsm[j*HWS + k]; float2 h = A[k];
                    av = fmaf(w, h.x, av); ad = fmaf(w, h.y, ad);
                }
                float p = av + c2;
                B[j] = make_float2(fmaxf(p, 0.f), p > 0.f ? ad : 0.f);
            }
            __syncthreads();
            for (int idx = j; idx < HD*HD; idx += HD) {
                int jj = idx >> 7, k = idx & 127;
                hsm[jj*HWS + k] = W3[b*HD*HD + idx];
            }
            __syncthreads();
            {
                float av = 0.f, ad = 0.f;
                #pragma unroll 8
                for (int k = 0; k < HD; ++k) {
                    float w = hsm[j*HWS + k]; float2 h = B[k];
                    av = fmaf(w, h.x, av); ad = fmaf(w, h.y, ad);
                }
                float p = av + c3;
                A[j] = make_float2(fmaxf(p, 0.f), p > 0.f ? ad : 0.f);
            }
            __syncthreads();
            red[j] = make_float2(w4 * A[j].x, w4 * A[j].y);
            __syncthreads();
            for (int s = 64; s > 0; s >>= 1) {
                if (j < s) { red[j].x += red[j+s].x; red[j].y += red[j+s].y; }
                __syncthreads();
            }
            if (j == 0) g_head[b][n] = make_float2(red[0].x + b4[b], red[0].y);
            __syncthreads();
        }
    }
}

// ---------------------------------------------------------------------------
// Main kernel: 64 samples/CTA, scaled-fp16 9-pass scheme, B grouped by level
// with cp.async prefetch of the next weight set.
// ---------------------------------------------------------------------------
__global__ __launch_bounds__(NT, 1)
void main_kernel(const float* __restrict__ t,
    const float* __restrict__ W1, const float* __restrict__ b1,
    const float* __restrict__ b2, const float* __restrict__ b3,
    const float* __restrict__ W4, const float* __restrict__ b4,
    float* __restrict__ out, int N)
{
    extern __shared__ char smem_raw[];
    const uint32_t sb_raw = (uint32_t)__cvta_generic_to_shared(smem_raw);
    const uint32_t sb = (sb_raw + 1023u) & ~1023u;
    char* smA = smem_raw + (sb - sb_raw);

    const int tid  = threadIdx.x;
    const int lane = tid & 31;
    const int w    = tid >> 5;
    const int m0   = (w >> 2) * 16;     // warp's 16-row slab (M=64)
    const int wn   = w & 3;
    const int n0   = wn * 32;           // warp's 32-col slab

    float*  sW1 = (float*)(smA + OFF_MISC) + 0;
    float*  sC1 = (float*)(smA + OFF_MISC) + 128;
    float*  sB2 = (float*)(smA + OFF_MISC) + 256;
    float*  sB3 = (float*)(smA + OFF_MISC) + 384;
    float*  sW4 = (float*)(smA + OFF_MISC) + 512;
    float*  sT  = (float*)(smA + OFF_MISC) + 640;     // 64 floats
    float2* red = (float2*)(smA + OFF_MISC + 2816);   // [64][4]

    const int base = blockIdx.x * MT;
    if (tid < MT) sT[tid] = t[base + tid];

    const uint32_t AVH = sb + OFF_AVH, AVM = sb + OFF_AVM, AVL = sb + OFF_AVL;
    const uint32_t ADH = sb + OFF_ADH, ADL = sb + OFF_ADL;
    const uint32_t BH  = sb + OFF_BH,  BM  = sb + OFF_BM,  BL  = sb + OFF_BL;

    // initial prefetch of iteration 0 (branch 0, W2)
    {
        const uint4* src = (const uint4*)g_Bsplit[0];
        prefetch_level(src,        BH, tid);
        prefetch_level(src + 2048, BM, tid);
        prefetch_level(src + 4096, BL, tid);
    }

    for (int b = 0; b < 3; ++b) {
        if (tid < HD) {
            sW1[tid] = W1[b*HD + tid];
            sC1[tid] = b1[b*HD + tid];
            sB2[tid] = b2[b*HD + tid];
            sB3[tid] = b3[b*HD + tid];
            sW4[tid] = W4[b*HD + tid];
        }
        if (b == 0) CP_WAIT0();
        __syncthreads();

        // ---- layer 1: elementwise -> A split buffers ----
        #pragma unroll
        for (int i = 0; i < 2; ++i) {
            int g = tid + i * NT;          // 0..1023
            int r = g >> 4, c0 = (g & 15) * 8;
            float tv = sT[r];
            float hv[8], hd[8];
            #pragma unroll
            for (int q = 0; q < 8; ++q) {
                float wv  = sW1[c0 + q];
                float pre = fmaf(tv, wv, sC1[c0 + q]);
                bool mk = pre > 0.f;
                hv[q] = mk ? pre : 0.f;
                hd[q] = mk ? wv  : 0.f;
            }
            uint4 vh, vm, vl, dh, dl;
            split3f_pair(hv[0], hv[1], vh.x, vm.x, vl.x);
            split3f_pair(hv[2], hv[3], vh.y, vm.y, vl.y);
            split3f_pair(hv[4], hv[5], vh.z, vm.z, vl.z);
            split3f_pair(hv[6], hv[7], vh.w, vm.w, vl.w);
            split2f_pair(hd[0], hd[1], dh.x, dl.x);
            split2f_pair(hd[2], hd[3], dh.y, dl.y);
            split2f_pair(hd[4], hd[5], dh.z, dl.z);
            split2f_pair(hd[6], hd[7], dh.w, dl.w);
            uint32_t ao = swz8(r, c0 >> 3);
            *(uint4*)(smA + OFF_AVH + ao) = vh;
            *(uint4*)(smA + OFF_AVM + ao) = vm;
            *(uint4*)(smA + OFF_AVL + ao) = vl;
            *(uint4*)(smA + OFF_ADH + ao) = dh;
            *(uint4*)(smA + OFF_ADL + ao) = dl;
        }
        __syncthreads();

        #pragma unroll 1
        for (int layer = 0; layer < 2; ++layer) {
            const int nxt = 2*b + layer + 1;    // next weight-set iteration

            float acc1[4][4], acc2[4][4], acc3[4][4], accd1[4][4], accd2[4][4];
            #pragma unroll
            for (int nt = 0; nt < 4; ++nt)
                #pragma unroll
                for (int q = 0; q < 4; ++q) {
                    acc1[nt][q]=0.f; acc2[nt][q]=0.f; acc3[nt][q]=0.f;
                    accd1[nt][q]=0.f; accd2[nt][q]=0.f;
                }

            // ---- group H: B=WH ----
            #pragma unroll
            for (int ks = 0; ks < 8; ++ks) {
                const int ch = ks * 2;
                uint32_t avh[4], avm[4], avl[4], adh[4], adl[4], bq[2][4];
                ldmA(avh, AVH, m0, ch, lane);
                ldmA(avm, AVM, m0, ch, lane);
                ldmA(avl, AVL, m0, ch, lane);
                ldmA(adh, ADH, m0, ch, lane);
                ldmA(adl, ADL, m0, ch, lane);
                ldmB(bq[0], BH, n0, ch, lane); ldmB(bq[1], BH, n0 + 16, ch, lane);
                #pragma unroll
                for (int nt = 0; nt < 4; ++nt) {
                    uint32_t b0 = bq[nt>>1][(nt&1)*2], b1 = bq[nt>>1][(nt&1)*2+1];
                    mma_f16(acc1[nt],  avh, b0, b1);
                    mma_f16(accd1[nt], adh, b0, b1);
                    mma_f16(acc2[nt],  avm, b0, b1);
                    mma_f16(accd2[nt], adl, b0, b1);
                    mma_f16(acc3[nt],  avl, b0, b1);
                }
            }
            __syncthreads();
            if (nxt < 6) prefetch_level((const uint4*)g_Bsplit[nxt], BH, tid);

            // ---- group M: B=WM ----
            #pragma unroll
            for (int ks = 0; ks < 8; ++ks) {
                const int ch = ks * 2;
                uint32_t avh[4], avm[4], adh[4], bq[2][4];
                ldmA(avh, AVH, m0, ch, lane);
                ldmA(avm, AVM, m0, ch, lane);
                ldmA(adh, ADH, m0, ch, lane);
                ldmB(bq[0], BM, n0, ch, lane); ldmB(bq[1], BM, n0 + 16, ch, lane);
                #pragma unroll
                for (int nt = 0; nt < 4; ++nt) {
                    uint32_t b0 = bq[nt>>1][(nt&1)*2], b1 = bq[nt>>1][(nt&1)*2+1];
                    mma_f16(acc2[nt],  avh, b0, b1);
                    mma_f16(acc3[nt],  avm, b0, b1);
                    mma_f16(accd2[nt], adh, b0, b1);
                }
            }
            __syncthreads();
            if (nxt < 6) prefetch_level((const uint4*)g_Bsplit[nxt] + 2048, BM, tid);

            // ---- group L: B=WL ----
            #pragma unroll
            for (int ks = 0; ks < 8; ++ks) {
                const int ch = ks * 2;
                uint32_t avh[4], bq[2][4];
                ldmA(avh, AVH, m0, ch, lane);
                ldmB(bq[0], BL, n0, ch, lane); ldmB(bq[1], BL, n0 + 16, ch, lane);
                #pragma unroll
                for (int nt = 0; nt < 4; ++nt)
                    mma_f16(acc3[nt], avh, bq[nt>>1][(nt&1)*2], bq[nt>>1][(nt&1)*2+1]);
            }
            __syncthreads();
            if (nxt < 6) prefetch_level((const uint4*)g_Bsplit[nxt] + 4096, BL, tid);

            if (layer == 0) {
                // ---- epilogue 2: combine + bias + relu + resplit -> A ----
                float bb[8];
                #pragma unroll
                for (int nt = 0; nt < 4; ++nt) {
                    int c = n0 + 8*nt + (lane & 3)*2;
                    bb[2*nt] = sB2[c]; bb[2*nt+1] = sB2[c+1];
                }
                #pragma unroll
                for (int h = 0; h < 2; ++h) {
                    int row = m0 + 8*h + (lane >> 2);
                    #pragma unroll
                    for (int nt = 0; nt < 4; ++nt) {
                        int c = n0 + 8*nt + (lane & 3)*2;
                        float p0 = acc1[nt][2*h]   + fmaf(acc2[nt][2*h],   S_DN,
                                     fmaf(acc3[nt][2*h],   S_DN2, bb[2*nt]));
                        float p1 = acc1[nt][2*h+1] + fmaf(acc2[nt][2*h+1], S_DN,
                                     fmaf(acc3[nt][2*h+1], S_DN2, bb[2*nt+1]));
                        bool q0 = p0 > 0.f, q1 = p1 > 0.f;
                        float v0 = q0 ? p0 : 0.f, v1 = q1 ? p1 : 0.f;
                        float d0 = q0 ? fmaf(accd2[nt][2*h],   S_DN, accd1[nt][2*h])   : 0.f;
                        float d1 = q1 ? fmaf(accd2[nt][2*h+1], S_DN, accd1[nt][2*h+1]) : 0.f;
                        uint32_t vh, vm, vl, dh, dl;
                        split3f_pair(v0, v1, vh, vm, vl);
                        split2f_pair(d0, d1, dh, dl);
                        uint32_t ao = swz8(row, c >> 3) + ((c & 7) << 1);
                        *(uint32_t*)(smA + OFF_AVH + ao) = vh;
                        *(uint32_t*)(smA + OFF_AVM + ao) = vm;
                        *(uint32_t*)(smA + OFF_AVL + ao) = vl;
                        *(uint32_t*)(smA + OFF_ADH + ao) = dh;
                        *(uint32_t*)(smA + OFF_ADL + ao) = dl;
                    }
                }
                CP_WAIT0();
                __syncthreads();
            } else {
                // ---- epilogue 3: combine + bias + relu + dot(w4) + post ----
                float bb[8], ww[8];
                #pragma unroll
                for (int nt = 0; nt < 4; ++nt) {
                    int c = n0 + 8*nt + (lane & 3)*2;
                    bb[2*nt] = sB3[c]; bb[2*nt+1] = sB3[c+1];
                    ww[2*nt] = sW4[c]; ww[2*nt+1] = sW4[c+1];
                }
                #pragma unroll
                for (int h = 0; h < 2; ++h) {
                    int row = m0 + 8*h + (lane >> 2);
                    float sv = 0.f, sd = 0.f;
                    #pragma unroll
                    for (int nt = 0; nt < 4; ++nt) {
                        float p0 = acc1[nt][2*h]   + fmaf(acc2[nt][2*h],   S_DN,
                                     fmaf(acc3[nt][2*h],   S_DN2, bb[2*nt]));
                        float p1 = acc1[nt][2*h+1] + fmaf(acc2[nt][2*h+1], S_DN,
                                     fmaf(acc3[nt][2*h+1], S_DN2, bb[2*nt+1]));
                        bool q0 = p0 > 0.f, q1 = p1 > 0.f;
                        float d0 = fmaf(accd2[nt][2*h],   S_DN, accd1[nt][2*h]);
                        float d1 = fmaf(accd2[nt][2*h+1], S_DN, accd1[nt][2*h+1]);
                        sv = fmaf(q0 ? p0 : 0.f, ww[2*nt],   sv);
                        sv = fmaf(q1 ? p1 : 0.f, ww[2*nt+1], sv);
                        sd = fmaf(q0 ? d0 : 0.f, ww[2*nt],   sd);
                        sd = fmaf(q1 ? d1 : 0.f, ww[2*nt+1], sd);
                    }
                    sv += __shfl_xor_sync(0xffffffffu, sv, 1);
                    sv += __shfl_xor_sync(0xffffffffu, sv, 2);
                    sd += __shfl_xor_sync(0xffffffffu, sd, 1);
                    sd += __shfl_xor_sync(0xffffffffu, sd, 2);
                    if ((lane & 3) == 0) red[row*4 + wn] = make_float2(sv, sd);
                }
                CP_WAIT0();
                __syncthreads();

                if (tid < MT) {
                    float2 r0 = red[tid*4+0], r1 = red[tid*4+1],
                           r2 = red[tid*4+2], r3 = red[tid*4+3];
                    float v  = r0.x + r1.x + r2.x + r3.x + b4[b];
                    float dv = r0.y + r1.y + r2.y + r3.y;
                    float2 h0 = g_head[b][0];
                    float2 h1 = g_head[b][1];
                    float s = (b == 1) ? -1.f : 1.f;
                    float d1 = h1.x - h0.x;
                    float sg1 = (d1 > 0.f) ? 1.f : ((d1 < 0.f) ? -1.f : 0.f);
                    float dsign1 = s * sg1 * h1.y;
                    int n = base + tid;
                    float d = v - h0.x;
                    float vv, ds;
                    if (n == 0) {
                        vv = 0.f;
                        ds = (dsign1 >= 0.f) ? fabsf(dv) : -fabsf(dv);
                    } else {
                        float sg = (d > 0.f) ? 1.f : ((d < 0.f) ? -1.f : 0.f);
                        vv = s * fabsf(d);
                        ds = s * sg * dv;
                    }
                    out[b*N + n]       = vv;
                    out[(3 + b)*N + n] = ds;
                }
                __syncthreads();
            }
        }
    }
}

// ---------------------------------------------------------------------------
extern "C" void kernel_launch(void* const* d_in, const int* in_sizes, int n_in,
                              void* d_out, int out_size)
{
    const float* t  = (const float*)d_in[0];
    const float* W1 = (const float*)d_in[1];
    const float* b1 = (const float*)d_in[2];
    const float* W2 = (const float*)d_in[3];
    const float* b2 = (const float*)d_in[4];
    const float* W3 = (const float*)d_in[5];
    const float* b3 = (const float*)d_in[6];
    const float* W4 = (const float*)d_in[7];
    const float* b4 = (const float*)d_in[8];
    float* out = (float*)d_out;
    const int N = in_sizes[0];

    const int HEAD_SMEM = HD * HWS * 4;

    cudaFuncSetAttribute(main_kernel, cudaFuncAttributeMaxDynamicSharedMemorySize, MAIN_SMEM);
    cudaFuncSetAttribute(head_kernel, cudaFuncAttributeMaxDynamicSharedMemorySize, HEAD_SMEM);

    prep_kernel<<<6, 256>>>(W2, W3);
    head_kernel<<<1, HD, HEAD_SMEM>>>(t, W1, b1, W2, b2, W3, b3, W4, b4);
    main_kernel<<<N / MT, NT, MAIN_SMEM>>>(t, W1, b1, b2, b3, W4, b4, out, N);
}

// round 10
// speedup vs baseline: 1.4152x; 1.2111x over previous
#include <cuda_runtime.h>
#include <cuda_fp16.h>
#include <cstdint>

#define HD 128
#define NT 512
#define MT 64

// byte offsets in the 1024-aligned dynamic smem region
#define OFF_AVH 0u
#define OFF_AVM 16384u
#define OFF_AVL 32768u
#define OFF_ADH 49152u
#define OFF_BH  65536u
#define OFF_BM  98304u
#define OFF_BL  131072u
#define OFF_MISC 163840u
#define MAIN_SMEM (163840 + 8192 + 1024)

#define S_UP   2048.0f                  // 2^11
#define S_DN   4.8828125e-4f            // 2^-11
#define S_DN2  2.384185791015625e-7f    // 2^-22

__device__ float2 g_head[3][2];
// pre-split swizzled weight tiles per iteration (iter = 2*branch + layer):
// levels H/M/L each 8192 u32 (32KB)
__device__ uint32_t g_Bsplit[6][3 * 8192];

// ---------------------------------------------------------------------------
// scaled fp16 split helpers
// ---------------------------------------------------------------------------
__device__ __forceinline__ float f16_rn(float x, uint32_t& bits) {
    __half h = __float2half_rn(x);
    bits = (uint32_t)__half_as_ushort(h);
    return __half2float(h);
}
// packed f16x2 with a in the LOW half
__device__ __forceinline__ uint32_t pack_f16_pair(float a, float b) {
    uint32_t r;
    asm("cvt.rn.f16x2.f32 %0, %1, %2;" : "=r"(r) : "f"(b), "f"(a));
    return r;
}
// x ≈ h + m*2^-11 + l*2^-22 ; all three stored values normal-range
__device__ __forceinline__ void split3f_pair(float a, float b,
                                             uint32_t& h, uint32_t& m, uint32_t& l) {
    uint32_t ha, ma, la, hb, mb, lb;
    float f = f16_rn(a, ha); float r = (a - f) * S_UP;
    f = f16_rn(r, ma);       float r2 = (r - f) * S_UP;
    f16_rn(r2, la);
    f = f16_rn(b, hb);       r = (b - f) * S_UP;
    f = f16_rn(r, mb);       r2 = (r - f) * S_UP;
    f16_rn(r2, lb);
    h = ha | (hb << 16); m = ma | (mb << 16); l = la | (lb << 16);
}

// swizzled byte offset inside a [rows x 128 f16] tile (row stride 256B)
__device__ __forceinline__ uint32_t swz8(int row, int col8) {
    return (uint32_t)(row * 256) + ((uint32_t)((col8 ^ (row & 7))) << 4);
}

// ---------------------------------------------------------------------------
// ldmatrix / mma wrappers (baseline PTX, compute_103-safe)
// ---------------------------------------------------------------------------
__device__ __forceinline__ void ldmA(uint32_t f[4], uint32_t base, int r0, int ch, int lane) {
    int g = lane >> 3, i = lane & 7;
    int row = r0 + i + ((g & 1) << 3);
    int c   = ch + (g >> 1);
    uint32_t addr = base + swz8(row, c);
    asm volatile("ldmatrix.sync.aligned.m8n8.x4.shared.b16 {%0,%1,%2,%3}, [%4];"
                 : "=r"(f[0]), "=r"(f[1]), "=r"(f[2]), "=r"(f[3]) : "r"(addr));
}
__device__ __forceinline__ void ldmB(uint32_t f[4], uint32_t base, int n0, int ch, int lane) {
    int g = lane >> 3, i = lane & 7;
    int row = n0 + i + ((g >> 1) << 3);
    int c   = ch + (g & 1);
    uint32_t addr = base + swz8(row, c);
    asm volatile("ldmatrix.sync.aligned.m8n8.x4.shared.b16 {%0,%1,%2,%3}, [%4];"
                 : "=r"(f[0]), "=r"(f[1]), "=r"(f[2]), "=r"(f[3]) : "r"(addr));
}
__device__ __forceinline__ void mma_f16(float c[4], const uint32_t a[4],
                                        uint32_t b0, uint32_t b1) {
    asm volatile("mma.sync.aligned.m16n8k16.row.col.f32.f16.f16.f32 "
                 "{%0,%1,%2,%3}, {%4,%5,%6,%7}, {%8,%9}, {%0,%1,%2,%3};"
                 : "+f"(c[0]), "+f"(c[1]), "+f"(c[2]), "+f"(c[3])
                 : "r"(a[0]), "r"(a[1]), "r"(a[2]), "r"(a[3]), "r"(b0), "r"(b1));
}

// cp.async one 32KB level (2048 uint4) GMEM -> SMEM, 4 x 16B per thread
__device__ __forceinline__ void prefetch_level(const uint4* __restrict__ src,
                                               uint32_t dst, int tid) {
    #pragma unroll
    for (int i = 0; i < 4; ++i) {
        uint32_t d = dst + (uint32_t)(tid + i * NT) * 16u;
        const uint4* s = src + tid + i * NT;
        asm volatile("cp.async.cg.shared.global [%0], [%1], 16;"
                     :: "r"(d), "l"(s) : "memory");
    }
    asm volatile("cp.async.commit_group;" ::: "memory");
}
#define CP_WAIT0() asm volatile("cp.async.wait_group 0;" ::: "memory")

// ---------------------------------------------------------------------------
// Prep kernel: split W2/W3 of every branch into swizzled scaled-fp16 tiles
// ---------------------------------------------------------------------------
__global__ void prep_kernel(const float* __restrict__ W2,
                            const float* __restrict__ W3)
{
    int iter = blockIdx.x;          // 0..5
    int b = iter >> 1, l = iter & 1;
    const float* W = (l ? W3 : W2) + b * HD * HD;
    char* dst = (char*)g_Bsplit[iter];
    for (int g = threadIdx.x; g < 2048; g += blockDim.x) {
        int j = g >> 4;
        int kg = (g & 15) * 8;
        float4 w0 = *(const float4*)(W + j * HD + kg);
        float4 w1 = *(const float4*)(W + j * HD + kg + 4);
        uint4 h, m, lo;
        split3f_pair(w0.x, w0.y, h.x, m.x, lo.x);
        split3f_pair(w0.z, w0.w, h.y, m.y, lo.y);
        split3f_pair(w1.x, w1.y, h.z, m.z, lo.z);
        split3f_pair(w1.z, w1.w, h.w, m.w, lo.w);
        uint32_t ao = swz8(j, kg >> 3);
        *(uint4*)(dst + ao)         = h;
        *(uint4*)(dst + 32768 + ao) = m;
        *(uint4*)(dst + 65536 + ao) = lo;
    }
}

// ---------------------------------------------------------------------------
// Head kernel (known-good fp32): (v, dv) at n=0,1 for all branches
// ---------------------------------------------------------------------------
#define HWS 129
__global__ void head_kernel(const float* __restrict__ t,
    const float* __restrict__ W1, const float* __restrict__ b1,
    const float* __restrict__ W2, const float* __restrict__ b2,
    const float* __restrict__ W3, const float* __restrict__ b3,
    const float* __restrict__ W4, const float* __restrict__ b4)
{
    extern __shared__ float hsm[];
    __shared__ float2 A[HD], B[HD];
    __shared__ float2 red[HD];
    const int j = threadIdx.x;
    float tv0 = t[0], tv1 = t[1];

    for (int b = 0; b < 3; ++b) {
        float w1 = W1[b*HD + j];
        float c1 = b1[b*HD + j];
        float c2 = b2[b*HD + j];
        float c3 = b3[b*HD + j];
        float w4 = W4[b*HD + j];
        for (int n = 0; n < 2; ++n) {
            float tn = (n == 0) ? tv0 : tv1;
            float pre = fmaf(tn, w1, c1);
            A[j] = make_float2(fmaxf(pre, 0.f), pre > 0.f ? w1 : 0.f);
            __syncthreads();
            for (int idx = j; idx < HD*HD; idx += HD) {
                int jj = idx >> 7, k = idx & 127;
                hsm[jj*HWS + k] = W2[b*HD*HD + idx];
            }
            __syncthreads();
            {
                float av = 0.f, ad = 0.f;
                #pragma unroll 8
                for (int k = 0; k < HD; ++k) {
                    float w = hsm[j*HWS + k]; float2 h = A[k];
                    av = fmaf(w, h.x, av); ad = fmaf(w, h.y, ad);
                }
                float p = av + c2;
                B[j] = make_float2(fmaxf(p, 0.f), p > 0.f ? ad : 0.f);
            }
            __syncthreads();
            for (int idx = j; idx < HD*HD; idx += HD) {
                int jj = idx >> 7, k = idx & 127;
                hsm[jj*HWS + k] = W3[b*HD*HD + idx];
            }
            __syncthreads();
            {
                float av = 0.f, ad = 0.f;
                #pragma unroll 8
                for (int k = 0; k < HD; ++k) {
                    float w = hsm[j*HWS + k]; float2 h = B[k];
                    av = fmaf(w, h.x, av); ad = fmaf(w, h.y, ad);
                }
                float p = av + c3;
                A[j] = make_float2(fmaxf(p, 0.f), p > 0.f ? ad : 0.f);
            }
            __syncthreads();
            red[j] = make_float2(w4 * A[j].x, w4 * A[j].y);
            __syncthreads();
            for (int s = 64; s > 0; s >>= 1) {
                if (j < s) { red[j].x += red[j+s].x; red[j].y += red[j+s].y; }
                __syncthreads();
            }
            if (j == 0) g_head[b][n] = make_float2(red[0].x + b4[b], red[0].y);
            __syncthreads();
        }
    }
}

// ---------------------------------------------------------------------------
// Main kernel: 64 samples/CTA. Value = 6-pass scaled-fp16 (3x3 split, split
// accumulators); tangent = single fp16 level vs B's H and M (2 passes).
// Fused 10-LDSM / 32-HMMA inner loop; all-at-once cp.async prefetch.
// ---------------------------------------------------------------------------
__global__ __launch_bounds__(NT, 1)
void main_kernel(const float* __restrict__ t,
    const float* __restrict__ W1, const float* __restrict__ b1,
    const float* __restrict__ b2, const float* __restrict__ b3,
    const float* __restrict__ W4, const float* __restrict__ b4,
    float* __restrict__ out, int N)
{
    extern __shared__ char smem_raw[];
    const uint32_t sb_raw = (uint32_t)__cvta_generic_to_shared(smem_raw);
    const uint32_t sb = (sb_raw + 1023u) & ~1023u;
    char* smA = smem_raw + (sb - sb_raw);

    const int tid  = threadIdx.x;
    const int lane = tid & 31;
    const int w    = tid >> 5;
    const int m0   = (w >> 2) * 16;     // warp's 16-row slab (M=64)
    const int wn   = w & 3;
    const int n0   = wn * 32;           // warp's 32-col slab

    float*  sW1 = (float*)(smA + OFF_MISC) + 0;
    float*  sC1 = (float*)(smA + OFF_MISC) + 128;
    float*  sB2 = (float*)(smA + OFF_MISC) + 256;
    float*  sB3 = (float*)(smA + OFF_MISC) + 384;
    float*  sW4 = (float*)(smA + OFF_MISC) + 512;
    float*  sT  = (float*)(smA + OFF_MISC) + 640;     // 64 floats
    float2* red = (float2*)(smA + OFF_MISC + 2816);   // [64][4]

    const int base = blockIdx.x * MT;
    if (tid < MT) sT[tid] = t[base + tid];

    const uint32_t AVH = sb + OFF_AVH, AVM = sb + OFF_AVM, AVL = sb + OFF_AVL;
    const uint32_t ADH = sb + OFF_ADH;
    const uint32_t BH  = sb + OFF_BH,  BM  = sb + OFF_BM,  BL  = sb + OFF_BL;

    // initial prefetch of iteration 0 (branch 0, W2)
    {
        const uint4* src = (const uint4*)g_Bsplit[0];
        prefetch_level(src,        BH, tid);
        prefetch_level(src + 2048, BM, tid);
        prefetch_level(src + 4096, BL, tid);
    }

    for (int b = 0; b < 3; ++b) {
        if (tid < HD) {
            sW1[tid] = W1[b*HD + tid];
            sC1[tid] = b1[b*HD + tid];
            sB2[tid] = b2[b*HD + tid];
            sB3[tid] = b3[b*HD + tid];
            sW4[tid] = W4[b*HD + tid];
        }
        if (b == 0) CP_WAIT0();
        __syncthreads();

        // ---- layer 1: elementwise -> A split buffers ----
        #pragma unroll
        for (int i = 0; i < 2; ++i) {
            int g = tid + i * NT;          // 0..1023
            int r = g >> 4, c0 = (g & 15) * 8;
            float tv = sT[r];
            float hv[8], hd[8];
            #pragma unroll
            for (int q = 0; q < 8; ++q) {
                float wv  = sW1[c0 + q];
                float pre = fmaf(tv, wv, sC1[c0 + q]);
                bool mk = pre > 0.f;
                hv[q] = mk ? pre : 0.f;
                hd[q] = mk ? wv  : 0.f;
            }
            uint4 vh, vm, vl, dh;
            split3f_pair(hv[0], hv[1], vh.x, vm.x, vl.x);
            split3f_pair(hv[2], hv[3], vh.y, vm.y, vl.y);
            split3f_pair(hv[4], hv[5], vh.z, vm.z, vl.z);
            split3f_pair(hv[6], hv[7], vh.w, vm.w, vl.w);
            dh.x = pack_f16_pair(hd[0], hd[1]);
            dh.y = pack_f16_pair(hd[2], hd[3]);
            dh.z = pack_f16_pair(hd[4], hd[5]);
            dh.w = pack_f16_pair(hd[6], hd[7]);
            uint32_t ao = swz8(r, c0 >> 3);
            *(uint4*)(smA + OFF_AVH + ao) = vh;
            *(uint4*)(smA + OFF_AVM + ao) = vm;
            *(uint4*)(smA + OFF_AVL + ao) = vl;
            *(uint4*)(smA + OFF_ADH + ao) = dh;
        }
        __syncthreads();

        #pragma unroll 1
        for (int layer = 0; layer < 2; ++layer) {
            const int nxt = 2*b + layer + 1;    // next weight-set iteration

            float acc1[4][4], acc2[4][4], acc3[4][4], accd1[4][4], accd2[4][4];
            #pragma unroll
            for (int nt = 0; nt < 4; ++nt)
                #pragma unroll
                for (int q = 0; q < 4; ++q) {
                    acc1[nt][q]=0.f; acc2[nt][q]=0.f; acc3[nt][q]=0.f;
                    accd1[nt][q]=0.f; accd2[nt][q]=0.f;
                }

            // fused loop: 10 LDSM + 32 HMMA per ks
            #pragma unroll 1
            for (int ks = 0; ks < 8; ++ks) {
                const int ch = ks * 2;
                uint32_t avh[4], avm[4], avl[4], adh[4];
                uint32_t bh[2][4], bm[2][4], bl[2][4];
                ldmA(avh, AVH, m0, ch, lane);
                ldmA(avm, AVM, m0, ch, lane);
                ldmA(avl, AVL, m0, ch, lane);
                ldmA(adh, ADH, m0, ch, lane);
                ldmB(bh[0], BH, n0, ch, lane); ldmB(bh[1], BH, n0 + 16, ch, lane);
                ldmB(bm[0], BM, n0, ch, lane); ldmB(bm[1], BM, n0 + 16, ch, lane);
                ldmB(bl[0], BL, n0, ch, lane); ldmB(bl[1], BL, n0 + 16, ch, lane);
                #pragma unroll
                for (int nt = 0; nt < 4; ++nt) {
                    uint32_t b0h = bh[nt>>1][(nt&1)*2], b1h = bh[nt>>1][(nt&1)*2+1];
                    uint32_t b0m = bm[nt>>1][(nt&1)*2], b1m = bm[nt>>1][(nt&1)*2+1];
                    uint32_t b0l = bl[nt>>1][(nt&1)*2], b1l = bl[nt>>1][(nt&1)*2+1];
                    mma_f16(acc1[nt],  avh, b0h, b1h);
                    mma_f16(accd1[nt], adh, b0h, b1h);
                    mma_f16(acc2[nt],  avm, b0h, b1h);
                    mma_f16(acc3[nt],  avl, b0h, b1h);
                    mma_f16(acc2[nt],  avh, b0m, b1m);
                    mma_f16(accd2[nt], adh, b0m, b1m);
                    mma_f16(acc3[nt],  avm, b0m, b1m);
                    mma_f16(acc3[nt],  avh, b0l, b1l);
                }
            }
            __syncthreads();      // all warps done reading A + B
            if (nxt < 6) {
                const uint4* src = (const uint4*)g_Bsplit[nxt];
                prefetch_level(src,        BH, tid);
                prefetch_level(src + 2048, BM, tid);
                prefetch_level(src + 4096, BL, tid);
            }

            if (layer == 0) {
                // ---- epilogue 2: combine + bias + relu + resplit -> A ----
                float bb[8];
                #pragma unroll
                for (int nt = 0; nt < 4; ++nt) {
                    int c = n0 + 8*nt + (lane & 3)*2;
                    bb[2*nt] = sB2[c]; bb[2*nt+1] = sB2[c+1];
                }
                #pragma unroll
                for (int h = 0; h < 2; ++h) {
                    int row = m0 + 8*h + (lane >> 2);
                    #pragma unroll
                    for (int nt = 0; nt < 4; ++nt) {
                        int c = n0 + 8*nt + (lane & 3)*2;
                        float p0 = acc1[nt][2*h]   + fmaf(acc2[nt][2*h],   S_DN,
                                     fmaf(acc3[nt][2*h],   S_DN2, bb[2*nt]));
                        float p1 = acc1[nt][2*h+1] + fmaf(acc2[nt][2*h+1], S_DN,
                                     fmaf(acc3[nt][2*h+1], S_DN2, bb[2*nt+1]));
                        bool q0 = p0 > 0.f, q1 = p1 > 0.f;
                        float v0 = q0 ? p0 : 0.f, v1 = q1 ? p1 : 0.f;
                        float d0 = q0 ? fmaf(accd2[nt][2*h],   S_DN, accd1[nt][2*h])   : 0.f;
                        float d1 = q1 ? fmaf(accd2[nt][2*h+1], S_DN, accd1[nt][2*h+1]) : 0.f;
                        uint32_t vh, vm, vl;
                        split3f_pair(v0, v1, vh, vm, vl);
                        uint32_t dh = pack_f16_pair(d0, d1);
                        uint32_t ao = swz8(row, c >> 3) + ((c & 7) << 1);
                        *(uint32_t*)(smA + OFF_AVH + ao) = vh;
                        *(uint32_t*)(smA + OFF_AVM + ao) = vm;
                        *(uint32_t*)(smA + OFF_AVL + ao) = vl;
                        *(uint32_t*)(smA + OFF_ADH + ao) = dh;
                    }
                }
                CP_WAIT0();
                __syncthreads();
            } else {
                // ---- epilogue 3: combine + bias + relu + dot(w4) + post ----
                float bb[8], ww[8];
                #pragma unroll
                for (int nt = 0; nt < 4; ++nt) {
                    int c = n0 + 8*nt + (lane & 3)*2;
                    bb[2*nt] = sB3[c]; bb[2*nt+1] = sB3[c+1];
                    ww[2*nt] = sW4[c]; ww[2*nt+1] = sW4[c+1];
                }
                #pragma unroll
                for (int h = 0; h < 2; ++h) {
                    int row = m0 + 8*h + (lane >> 2);
                    float sv = 0.f, sd = 0.f;
                    #pragma unroll
                    for (int nt = 0; nt < 4; ++nt) {
                        float p0 = acc1[nt][2*h]   + fmaf(acc2[nt][2*h],   S_DN,
                                     fmaf(acc3[nt][2*h],   S_DN2, bb[2*nt]));
                        float p1 = acc1[nt][2*h+1] + fmaf(acc2[nt][2*h+1], S_DN,
                                     fmaf(acc3[nt][2*h+1], S_DN2, bb[2*nt+1]));
                        bool q0 = p0 > 0.f, q1 = p1 > 0.f;
                        float d0 = fmaf(accd2[nt][2*h],   S_DN, accd1[nt][2*h]);
                        float d1 = fmaf(accd2[nt][2*h+1], S_DN, accd1[nt][2*h+1]);
                        sv = fmaf(q0 ? p0 : 0.f, ww[2*nt],   sv);
                        sv = fmaf(q1 ? p1 : 0.f, ww[2*nt+1], sv);
                        sd = fmaf(q0 ? d0 : 0.f, ww[2*nt],   sd);
                        sd = fmaf(q1 ? d1 : 0.f, ww[2*nt+1], sd);
                    }
                    sv += __shfl_xor_sync(0xffffffffu, sv, 1);
                    sv += __shfl_xor_sync(0xffffffffu, sv, 2);
                    sd += __shfl_xor_sync(0xffffffffu, sd, 1);
                    sd += __shfl_xor_sync(0xffffffffu, sd, 2);
                    if ((lane & 3) == 0) red[row*4 + wn] = make_float2(sv, sd);
                }
                CP_WAIT0();
                __syncthreads();

                if (tid < MT) {
                    float2 r0 = red[tid*4+0], r1 = red[tid*4+1],
                           r2 = red[tid*4+2], r3 = red[tid*4+3];
                    float v  = r0.x + r1.x + r2.x + r3.x + b4[b];
                    float dv = r0.y + r1.y + r2.y + r3.y;
                    float2 h0 = g_head[b][0];
                    float2 h1 = g_head[b][1];
                    float s = (b == 1) ? -1.f : 1.f;
                    float d1 = h1.x - h0.x;
                    float sg1 = (d1 > 0.f) ? 1.f : ((d1 < 0.f) ? -1.f : 0.f);
                    float dsign1 = s * sg1 * h1.y;
                    int n = base + tid;
                    float d = v - h0.x;
                    float vv, ds;
                    if (n == 0) {
                        vv = 0.f;
                        ds = (dsign1 >= 0.f) ? fabsf(dv) : -fabsf(dv);
                    } else {
                        float sg = (d > 0.f) ? 1.f : ((d < 0.f) ? -1.f : 0.f);
                        vv = s * fabsf(d);
                        ds = s * sg * dv;
                    }
                    out[b*N + n]       = vv;
                    out[(3 + b)*N + n] = ds;
                }
                __syncthreads();
            }
        }
    }
}

// ---------------------------------------------------------------------------
extern "C" void kernel_launch(void* const* d_in, const int* in_sizes, int n_in,
                              void* d_out, int out_size)
{
    const float* t  = (const float*)d_in[0];
    const float* W1 = (const float*)d_in[1];
    const float* b1 = (const float*)d_in[2];
    const float* W2 = (const float*)d_in[3];
    const float* b2 = (const float*)d_in[4];
    const float* W3 = (const float*)d_in[5];
    const float* b3 = (const float*)d_in[6];
    const float* W4 = (const float*)d_in[7];
    const float* b4 = (const float*)d_in[8];
    float* out = (float*)d_out;
    const int N = in_sizes[0];

    const int HEAD_SMEM = HD * HWS * 4;

    cudaFuncSetAttribute(main_kernel, cudaFuncAttributeMaxDynamicSharedMemorySize, MAIN_SMEM);
    cudaFuncSetAttribute(head_kernel, cudaFuncAttributeMaxDynamicSharedMemorySize, HEAD_SMEM);

    prep_kernel<<<6, 256>>>(W2, W3);
    head_kernel<<<1, HD, HEAD_SMEM>>>(t, W1, b1, W2, b2, W3, b3, W4, b4);
    main_kernel<<<N / MT, NT, MAIN_SMEM>>>(t, W1, b1, b2, b3, W4, b4, out, N);
}

// round 11
// speedup vs baseline: 1.8116x; 1.2801x over previous
#include <cuda_runtime.h>
#include <cuda_fp16.h>
#include <cstdint>

#define HD 128
#define NT 512
#define MT 64

// byte offsets in the 1024-aligned dynamic smem region
#define OFF_AVH 0u
#define OFF_AVL 16384u
#define OFF_ADH 32768u
#define OFF_BH  49152u
#define OFF_BL  81920u
#define OFF_MISC 114688u
#define MAIN_SMEM (114688 + 8192 + 1024)

#define S_UP   2048.0f                  // 2^11
#define S_DN   4.8828125e-4f            // 2^-11
#define S_DN2  2.384185791015625e-7f    // 2^-22

__device__ float2 g_head[3][2];
// pre-split swizzled weight tiles per iteration (iter = 2*branch + layer):
// levels H/L each 8192 u32 (32KB)
__device__ uint32_t g_Bsplit[6][2 * 8192];

// ---------------------------------------------------------------------------
// scaled fp16 split helpers
// ---------------------------------------------------------------------------
__device__ __forceinline__ float f16_rn(float x, uint32_t& bits) {
    __half h = __float2half_rn(x);
    bits = (uint32_t)__half_as_ushort(h);
    return __half2float(h);
}
// packed f16x2 with a in the LOW half
__device__ __forceinline__ uint32_t pack_f16_pair(float a, float b) {
    uint32_t r;
    asm("cvt.rn.f16x2.f32 %0, %1, %2;" : "=r"(r) : "f"(b), "f"(a));
    return r;
}
// x ≈ h + l*2^-11 with l stored scaled by 2^11 (residual ~2^-24)
__device__ __forceinline__ void split2f_pair(float a, float b,
                                             uint32_t& h, uint32_t& l) {
    uint32_t ha, la, hb, lb;
    float f = f16_rn(a, ha); f16_rn((a - f) * S_UP, la);
    f = f16_rn(b, hb);       f16_rn((b - f) * S_UP, lb);
    h = ha | (hb << 16); l = la | (lb << 16);
}

// swizzled byte offset inside a [rows x 128 f16] tile (row stride 256B)
__device__ __forceinline__ uint32_t swz8(int row, int col8) {
    return (uint32_t)(row * 256) + ((uint32_t)((col8 ^ (row & 7))) << 4);
}

// ---------------------------------------------------------------------------
// ldmatrix / mma wrappers (baseline PTX, compute_103-safe)
// ---------------------------------------------------------------------------
__device__ __forceinline__ void ldmA(uint32_t f[4], uint32_t base, int r0, int ch, int lane) {
    int g = lane >> 3, i = lane & 7;
    int row = r0 + i + ((g & 1) << 3);
    int c   = ch + (g >> 1);
    uint32_t addr = base + swz8(row, c);
    asm volatile("ldmatrix.sync.aligned.m8n8.x4.shared.b16 {%0,%1,%2,%3}, [%4];"
                 : "=r"(f[0]), "=r"(f[1]), "=r"(f[2]), "=r"(f[3]) : "r"(addr));
}
__device__ __forceinline__ void ldmB(uint32_t f[4], uint32_t base, int n0, int ch, int lane) {
    int g = lane >> 3, i = lane & 7;
    int row = n0 + i + ((g >> 1) << 3);
    int c   = ch + (g & 1);
    uint32_t addr = base + swz8(row, c);
    asm volatile("ldmatrix.sync.aligned.m8n8.x4.shared.b16 {%0,%1,%2,%3}, [%4];"
                 : "=r"(f[0]), "=r"(f[1]), "=r"(f[2]), "=r"(f[3]) : "r"(addr));
}
__device__ __forceinline__ void mma_f16(float c[4], const uint32_t a[4],
                                        uint32_t b0, uint32_t b1) {
    asm volatile("mma.sync.aligned.m16n8k16.row.col.f32.f16.f16.f32 "
                 "{%0,%1,%2,%3}, {%4,%5,%6,%7}, {%8,%9}, {%0,%1,%2,%3};"
                 : "+f"(c[0]), "+f"(c[1]), "+f"(c[2]), "+f"(c[3])
                 : "r"(a[0]), "r"(a[1]), "r"(a[2]), "r"(a[3]), "r"(b0), "r"(b1));
}

// cp.async one 32KB level (2048 uint4) GMEM -> SMEM, 4 x 16B per thread
__device__ __forceinline__ void prefetch_level(const uint4* __restrict__ src,
                                               uint32_t dst, int tid) {
    #pragma unroll
    for (int i = 0; i < 4; ++i) {
        uint32_t d = dst + (uint32_t)(tid + i * NT) * 16u;
        const uint4* s = src + tid + i * NT;
        asm volatile("cp.async.cg.shared.global [%0], [%1], 16;"
                     :: "r"(d), "l"(s) : "memory");
    }
    asm volatile("cp.async.commit_group;" ::: "memory");
}
#define CP_WAIT0() asm volatile("cp.async.wait_group 0;" ::: "memory")

// ---------------------------------------------------------------------------
// Prep kernel: split W2/W3 of every branch into swizzled scaled-fp16 tiles
// ---------------------------------------------------------------------------
__global__ void prep_kernel(const float* __restrict__ W2,
                            const float* __restrict__ W3)
{
    int iter = blockIdx.x;          // 0..5
    int b = iter >> 1, l = iter & 1;
    const float* W = (l ? W3 : W2) + b * HD * HD;
    char* dst = (char*)g_Bsplit[iter];
    for (int g = threadIdx.x; g < 2048; g += blockDim.x) {
        int j = g >> 4;
        int kg = (g & 15) * 8;
        float4 w0 = *(const float4*)(W + j * HD + kg);
        float4 w1 = *(const float4*)(W + j * HD + kg + 4);
        uint4 h, lo;
        split2f_pair(w0.x, w0.y, h.x, lo.x);
        split2f_pair(w0.z, w0.w, h.y, lo.y);
        split2f_pair(w1.x, w1.y, h.z, lo.z);
        split2f_pair(w1.z, w1.w, h.w, lo.w);
        uint32_t ao = swz8(j, kg >> 3);
        *(uint4*)(dst + ao)         = h;
        *(uint4*)(dst + 32768 + ao) = lo;
    }
}

// ---------------------------------------------------------------------------
// Head kernel (known-good fp32): (v, dv) at n=0,1 for all branches
// ---------------------------------------------------------------------------
#define HWS 129
__global__ void head_kernel(const float* __restrict__ t,
    const float* __restrict__ W1, const float* __restrict__ b1,
    const float* __restrict__ W2, const float* __restrict__ b2,
    const float* __restrict__ W3, const float* __restrict__ b3,
    const float* __restrict__ W4, const float* __restrict__ b4)
{
    extern __shared__ float hsm[];
    __shared__ float2 A[HD], B[HD];
    __shared__ float2 red[HD];
    const int j = threadIdx.x;
    float tv0 = t[0], tv1 = t[1];

    for (int b = 0; b < 3; ++b) {
        float w1 = W1[b*HD + j];
        float c1 = b1[b*HD + j];
        float c2 = b2[b*HD + j];
        float c3 = b3[b*HD + j];
        float w4 = W4[b*HD + j];
        for (int n = 0; n < 2; ++n) {
            float tn = (n == 0) ? tv0 : tv1;
            float pre = fmaf(tn, w1, c1);
            A[j] = make_float2(fmaxf(pre, 0.f), pre > 0.f ? w1 : 0.f);
            __syncthreads();
            for (int idx = j; idx < HD*HD; idx += HD) {
                int jj = idx >> 7, k = idx & 127;
                hsm[jj*HWS + k] = W2[b*HD*HD + idx];
            }
            __syncthreads();
            {
                float av = 0.f, ad = 0.f;
                #pragma unroll 8
                for (int k = 0; k < HD; ++k) {
                    float w = hsm[j*HWS + k]; float2 h = A[k];
                    av = fmaf(w, h.x, av); ad = fmaf(w, h.y, ad);
                }
                float p = av + c2;
                B[j] = make_float2(fmaxf(p, 0.f), p > 0.f ? ad : 0.f);
            }
            __syncthreads();
            for (int idx = j; idx < HD*HD; idx += HD) {
                int jj = idx >> 7, k = idx & 127;
                hsm[jj*HWS + k] = W3[b*HD*HD + idx];
            }
            __syncthreads();
            {
                float av = 0.f, ad = 0.f;
                #pragma unroll 8
                for (int k = 0; k < HD; ++k) {
                    float w = hsm[j*HWS + k]; float2 h = B[k];
                    av = fmaf(w, h.x, av); ad = fmaf(w, h.y, ad);
                }
                float p = av + c3;
                A[j] = make_float2(fmaxf(p, 0.f), p > 0.f ? ad : 0.f);
            }
            __syncthreads();
            red[j] = make_float2(w4 * A[j].x, w4 * A[j].y);
            __syncthreads();
            for (int s = 64; s > 0; s >>= 1) {
                if (j < s) { red[j].x += red[j+s].x; red[j].y += red[j+s].y; }
                __syncthreads();
            }
            if (j == 0) g_head[b][n] = make_float2(red[0].x + b4[b], red[0].y);
            __syncthreads();
        }
    }
}

// ---------------------------------------------------------------------------
// Main kernel: 64 samples/CTA. Value = 4-pass 2-level scaled-fp16 split
// (residual 2^-24); tangent = single fp16 level vs B's H and L (2 passes).
// 7 LDSM / 24 HMMA per ks; cp.async prefetch of next weight set.
// ---------------------------------------------------------------------------
__global__ __launch_bounds__(NT, 1)
void main_kernel(const float* __restrict__ t,
    const float* __restrict__ W1, const float* __restrict__ b1,
    const float* __restrict__ b2, const float* __restrict__ b3,
    const float* __restrict__ W4, const float* __restrict__ b4,
    float* __restrict__ out, int N)
{
    extern __shared__ char smem_raw[];
    const uint32_t sb_raw = (uint32_t)__cvta_generic_to_shared(smem_raw);
    const uint32_t sb = (sb_raw + 1023u) & ~1023u;
    char* smA = smem_raw + (sb - sb_raw);

    const int tid  = threadIdx.x;
    const int lane = tid & 31;
    const int w    = tid >> 5;
    const int m0   = (w >> 2) * 16;     // warp's 16-row slab (M=64)
    const int wn   = w & 3;
    const int n0   = wn * 32;           // warp's 32-col slab

    float*  sW1 = (float*)(smA + OFF_MISC) + 0;
    float*  sC1 = (float*)(smA + OFF_MISC) + 128;
    float*  sB2 = (float*)(smA + OFF_MISC) + 256;
    float*  sB3 = (float*)(smA + OFF_MISC) + 384;
    float*  sW4 = (float*)(smA + OFF_MISC) + 512;
    float*  sT  = (float*)(smA + OFF_MISC) + 640;     // 64 floats
    float2* red = (float2*)(smA + OFF_MISC + 2816);   // [64][4]

    const int base = blockIdx.x * MT;
    if (tid < MT) sT[tid] = t[base + tid];

    const uint32_t AVH = sb + OFF_AVH, AVL = sb + OFF_AVL;
    const uint32_t ADH = sb + OFF_ADH;
    const uint32_t BH  = sb + OFF_BH,  BL  = sb + OFF_BL;

    // initial prefetch of iteration 0 (branch 0, W2)
    {
        const uint4* src = (const uint4*)g_Bsplit[0];
        prefetch_level(src,        BH, tid);
        prefetch_level(src + 2048, BL, tid);
    }

    for (int b = 0; b < 3; ++b) {
        if (tid < HD) {
            sW1[tid] = W1[b*HD + tid];
            sC1[tid] = b1[b*HD + tid];
            sB2[tid] = b2[b*HD + tid];
            sB3[tid] = b3[b*HD + tid];
            sW4[tid] = W4[b*HD + tid];
        }
        if (b == 0) CP_WAIT0();
        __syncthreads();

        // ---- layer 1: elementwise -> A split buffers ----
        #pragma unroll
        for (int i = 0; i < 2; ++i) {
            int g = tid + i * NT;          // 0..1023
            int r = g >> 4, c0 = (g & 15) * 8;
            float tv = sT[r];
            float hv[8], hd[8];
            #pragma unroll
            for (int q = 0; q < 8; ++q) {
                float wv  = sW1[c0 + q];
                float pre = fmaf(tv, wv, sC1[c0 + q]);
                bool mk = pre > 0.f;
                hv[q] = mk ? pre : 0.f;
                hd[q] = mk ? wv  : 0.f;
            }
            uint4 vh, vl, dh;
            split2f_pair(hv[0], hv[1], vh.x, vl.x);
            split2f_pair(hv[2], hv[3], vh.y, vl.y);
            split2f_pair(hv[4], hv[5], vh.z, vl.z);
            split2f_pair(hv[6], hv[7], vh.w, vl.w);
            dh.x = pack_f16_pair(hd[0], hd[1]);
            dh.y = pack_f16_pair(hd[2], hd[3]);
            dh.z = pack_f16_pair(hd[4], hd[5]);
            dh.w = pack_f16_pair(hd[6], hd[7]);
            uint32_t ao = swz8(r, c0 >> 3);
            *(uint4*)(smA + OFF_AVH + ao) = vh;
            *(uint4*)(smA + OFF_AVL + ao) = vl;
            *(uint4*)(smA + OFF_ADH + ao) = dh;
        }
        __syncthreads();

        #pragma unroll 1
        for (int layer = 0; layer < 2; ++layer) {
            const int nxt = 2*b + layer + 1;    // next weight-set iteration

            float acc1[4][4], acc2[4][4], acc3[4][4], accd1[4][4], accd2[4][4];
            #pragma unroll
            for (int nt = 0; nt < 4; ++nt)
                #pragma unroll
                for (int q = 0; q < 4; ++q) {
                    acc1[nt][q]=0.f; acc2[nt][q]=0.f; acc3[nt][q]=0.f;
                    accd1[nt][q]=0.f; accd2[nt][q]=0.f;
                }

            // fused loop: 7 LDSM + 24 HMMA per ks
            #pragma unroll 1
            for (int ks = 0; ks < 8; ++ks) {
                const int ch = ks * 2;
                uint32_t avh[4], avl[4], adh[4];
                uint32_t bh[2][4], bl[2][4];
                ldmA(avh, AVH, m0, ch, lane);
                ldmA(avl, AVL, m0, ch, lane);
                ldmA(adh, ADH, m0, ch, lane);
                ldmB(bh[0], BH, n0, ch, lane); ldmB(bh[1], BH, n0 + 16, ch, lane);
                ldmB(bl[0], BL, n0, ch, lane); ldmB(bl[1], BL, n0 + 16, ch, lane);
                #pragma unroll
                for (int nt = 0; nt < 4; ++nt) {
                    uint32_t b0h = bh[nt>>1][(nt&1)*2], b1h = bh[nt>>1][(nt&1)*2+1];
                    uint32_t b0l = bl[nt>>1][(nt&1)*2], b1l = bl[nt>>1][(nt&1)*2+1];
                    mma_f16(acc1[nt],  avh, b0h, b1h);
                    mma_f16(accd1[nt], adh, b0h, b1h);
                    mma_f16(acc2[nt],  avl, b0h, b1h);
                    mma_f16(acc2[nt],  avh, b0l, b1l);
                    mma_f16(accd2[nt], adh, b0l, b1l);
                    mma_f16(acc3[nt],  avl, b0l, b1l);
                }
            }
            __syncthreads();      // all warps done reading A + B
            if (nxt < 6) {
                const uint4* src = (const uint4*)g_Bsplit[nxt];
                prefetch_level(src,        BH, tid);
                prefetch_level(src + 2048, BL, tid);
            }

            if (layer == 0) {
                // ---- epilogue 2: combine + bias + relu + resplit -> A ----
                float bb[8];
                #pragma unroll
                for (int nt = 0; nt < 4; ++nt) {
                    int c = n0 + 8*nt + (lane & 3)*2;
                    bb[2*nt] = sB2[c]; bb[2*nt+1] = sB2[c+1];
                }
                #pragma unroll
                for (int h = 0; h < 2; ++h) {
                    int row = m0 + 8*h + (lane >> 2);
                    #pragma unroll
                    for (int nt = 0; nt < 4; ++nt) {
                        int c = n0 + 8*nt + (lane & 3)*2;
                        float p0 = acc1[nt][2*h]   + fmaf(acc2[nt][2*h],   S_DN,
                                     fmaf(acc3[nt][2*h],   S_DN2, bb[2*nt]));
                        float p1 = acc1[nt][2*h+1] + fmaf(acc2[nt][2*h+1], S_DN,
                                     fmaf(acc3[nt][2*h+1], S_DN2, bb[2*nt+1]));
                        bool q0 = p0 > 0.f, q1 = p1 > 0.f;
                        float v0 = q0 ? p0 : 0.f, v1 = q1 ? p1 : 0.f;
                        float d0 = q0 ? fmaf(accd2[nt][2*h],   S_DN, accd1[nt][2*h])   : 0.f;
                        float d1 = q1 ? fmaf(accd2[nt][2*h+1], S_DN, accd1[nt][2*h+1]) : 0.f;
                        uint32_t vh, vl;
                        split2f_pair(v0, v1, vh, vl);
                        uint32_t dh = pack_f16_pair(d0, d1);
                        uint32_t ao = swz8(row, c >> 3) + ((c & 7) << 1);
                        *(uint32_t*)(smA + OFF_AVH + ao) = vh;
                        *(uint32_t*)(smA + OFF_AVL + ao) = vl;
                        *(uint32_t*)(smA + OFF_ADH + ao) = dh;
                    }
                }
                CP_WAIT0();
                __syncthreads();
            } else {
                // ---- epilogue 3: combine + bias + relu + dot(w4) + post ----
                float bb[8], ww[8];
                #pragma unroll
                for (int nt = 0; nt < 4; ++nt) {
                    int c = n0 + 8*nt + (lane & 3)*2;
                    bb[2*nt] = sB3[c]; bb[2*nt+1] = sB3[c+1];
                    ww[2*nt] = sW4[c]; ww[2*nt+1] = sW4[c+1];
                }
                #pragma unroll
                for (int h = 0; h < 2; ++h) {
                    int row = m0 + 8*h + (lane >> 2);
                    float sv = 0.f, sd = 0.f;
                    #pragma unroll
                    for (int nt = 0; nt < 4; ++nt) {
                        float p0 = acc1[nt][2*h]   + fmaf(acc2[nt][2*h],   S_DN,
                                     fmaf(acc3[nt][2*h],   S_DN2, bb[2*nt]));
                        float p1 = acc1[nt][2*h+1] + fmaf(acc2[nt][2*h+1], S_DN,
                                     fmaf(acc3[nt][2*h+1], S_DN2, bb[2*nt+1]));
                        bool q0 = p0 > 0.f, q1 = p1 > 0.f;
                        float d0 = fmaf(accd2[nt][2*h],   S_DN, accd1[nt][2*h]);
                        float d1 = fmaf(accd2[nt][2*h+1], S_DN, accd1[nt][2*h+1]);
                        sv = fmaf(q0 ? p0 : 0.f, ww[2*nt],   sv);
                        sv = fmaf(q1 ? p1 : 0.f, ww[2*nt+1], sv);
                        sd = fmaf(q0 ? d0 : 0.f, ww[2*nt],   sd);
                        sd = fmaf(q1 ? d1 : 0.f, ww[2*nt+1], sd);
                    }
                    sv += __shfl_xor_sync(0xffffffffu, sv, 1);
                    sv += __shfl_xor_sync(0xffffffffu, sv, 2);
                    sd += __shfl_xor_sync(0xffffffffu, sd, 1);
                    sd += __shfl_xor_sync(0xffffffffu, sd, 2);
                    if ((lane & 3) == 0) red[row*4 + wn] = make_float2(sv, sd);
                }
                CP_WAIT0();
                __syncthreads();

                if (tid < MT) {
                    float2 r0 = red[tid*4+0], r1 = red[tid*4+1],
                           r2 = red[tid*4+2], r3 = red[tid*4+3];
                    float v  = r0.x + r1.x + r2.x + r3.x + b4[b];
                    float dv = r0.y + r1.y + r2.y + r3.y;
                    float2 h0 = g_head[b][0];
                    float2 h1 = g_head[b][1];
                    float s = (b == 1) ? -1.f : 1.f;
                    float d1 = h1.x - h0.x;
                    float sg1 = (d1 > 0.f) ? 1.f : ((d1 < 0.f) ? -1.f : 0.f);
                    float dsign1 = s * sg1 * h1.y;
                    int n = base + tid;
                    float d = v - h0.x;
                    float vv, ds;
                    if (n == 0) {
                        vv = 0.f;
                        ds = (dsign1 >= 0.f) ? fabsf(dv) : -fabsf(dv);
                    } else {
                        float sg = (d > 0.f) ? 1.f : ((d < 0.f) ? -1.f : 0.f);
                        vv = s * fabsf(d);
                        ds = s * sg * dv;
                    }
                    out[b*N + n]       = vv;
                    out[(3 + b)*N + n] = ds;
                }
                __syncthreads();
            }
        }
    }
}

// ---------------------------------------------------------------------------
extern "C" void kernel_launch(void* const* d_in, const int* in_sizes, int n_in,
                              void* d_out, int out_size)
{
    const float* t  = (const float*)d_in[0];
    const float* W1 = (const float*)d_in[1];
    const float* b1 = (const float*)d_in[2];
    const float* W2 = (const float*)d_in[3];
    const float* b2 = (const float*)d_in[4];
    const float* W3 = (const float*)d_in[5];
    const float* b3 = (const float*)d_in[6];
    const float* W4 = (const float*)d_in[7];
    const float* b4 = (const float*)d_in[8];
    float* out = (float*)d_out;
    const int N = in_sizes[0];

    const int HEAD_SMEM = HD * HWS * 4;

    cudaFuncSetAttribute(main_kernel, cudaFuncAttributeMaxDynamicSharedMemorySize, MAIN_SMEM);
    cudaFuncSetAttribute(head_kernel, cudaFuncAttributeMaxDynamicSharedMemorySize, HEAD_SMEM);

    prep_kernel<<<6, 256>>>(W2, W3);
    head_kernel<<<1, HD, HEAD_SMEM>>>(t, W1, b1, W2, b2, W3, b3, W4, b4);
    main_kernel<<<N / MT, NT, MAIN_SMEM>>>(t, W1, b1, b2, b3, W4, b4, out, N);
}

// round 12
// speedup vs baseline: 1.9203x; 1.0600x over previous
#include <cuda_runtime.h>
#include <cuda_fp16.h>
#include <cstdint>

#define HD 128
#define NT 256
#define MT 32

// byte offsets in the 1024-aligned dynamic smem region
#define OFF_AVH 0u
#define OFF_AVL 8192u
#define OFF_ADH 16384u
#define OFF_BH  24576u
#define OFF_BL  57344u
#define OFF_MISC 90112u
#define MAIN_SMEM (90112 + 4096 + 1024)

#define S_UP   2048.0f                  // 2^11
#define S_DN   4.8828125e-4f            // 2^-11
#define S_DN2  2.384185791015625e-7f    // 2^-22

__device__ float2 g_head[3][2];
// pre-split swizzled weight tiles per iteration (iter = 2*branch + layer):
// levels H/L each 8192 u32 (32KB)
__device__ uint32_t g_Bsplit[6][2 * 8192];

// ---------------------------------------------------------------------------
// scaled fp16 split helpers
// ---------------------------------------------------------------------------
__device__ __forceinline__ float f16_rn(float x, uint32_t& bits) {
    __half h = __float2half_rn(x);
    bits = (uint32_t)__half_as_ushort(h);
    return __half2float(h);
}
// packed f16x2 with a in the LOW half
__device__ __forceinline__ uint32_t pack_f16_pair(float a, float b) {
    uint32_t r;
    asm("cvt.rn.f16x2.f32 %0, %1, %2;" : "=r"(r) : "f"(b), "f"(a));
    return r;
}
// x ≈ h + l*2^-11 with l stored scaled by 2^11 (residual ~2^-24)
__device__ __forceinline__ void split2f_pair(float a, float b,
                                             uint32_t& h, uint32_t& l) {
    uint32_t ha, la, hb, lb;
    float f = f16_rn(a, ha); f16_rn((a - f) * S_UP, la);
    f = f16_rn(b, hb);       f16_rn((b - f) * S_UP, lb);
    h = ha | (hb << 16); l = la | (lb << 16);
}

// swizzled byte offset inside a [rows x 128 f16] tile (row stride 256B)
__device__ __forceinline__ uint32_t swz8(int row, int col8) {
    return (uint32_t)(row * 256) + ((uint32_t)((col8 ^ (row & 7))) << 4);
}

// ---------------------------------------------------------------------------
// ldmatrix / mma wrappers (baseline PTX, compute_103-safe)
// ---------------------------------------------------------------------------
__device__ __forceinline__ void ldmA(uint32_t f[4], uint32_t base, int r0, int ch, int lane) {
    int g = lane >> 3, i = lane & 7;
    int row = r0 + i + ((g & 1) << 3);
    int c   = ch + (g >> 1);
    uint32_t addr = base + swz8(row, c);
    asm volatile("ldmatrix.sync.aligned.m8n8.x4.shared.b16 {%0,%1,%2,%3}, [%4];"
                 : "=r"(f[0]), "=r"(f[1]), "=r"(f[2]), "=r"(f[3]) : "r"(addr));
}
__device__ __forceinline__ void ldmB(uint32_t f[4], uint32_t base, int n0, int ch, int lane) {
    int g = lane >> 3, i = lane & 7;
    int row = n0 + i + ((g >> 1) << 3);
    int c   = ch + (g & 1);
    uint32_t addr = base + swz8(row, c);
    asm volatile("ldmatrix.sync.aligned.m8n8.x4.shared.b16 {%0,%1,%2,%3}, [%4];"
                 : "=r"(f[0]), "=r"(f[1]), "=r"(f[2]), "=r"(f[3]) : "r"(addr));
}
__device__ __forceinline__ void mma_f16(float c[4], const uint32_t a[4],
                                        uint32_t b0, uint32_t b1) {
    asm volatile("mma.sync.aligned.m16n8k16.row.col.f32.f16.f16.f32 "
                 "{%0,%1,%2,%3}, {%4,%5,%6,%7}, {%8,%9}, {%0,%1,%2,%3};"
                 : "+f"(c[0]), "+f"(c[1]), "+f"(c[2]), "+f"(c[3])
                 : "r"(a[0]), "r"(a[1]), "r"(a[2]), "r"(a[3]), "r"(b0), "r"(b1));
}

// cp.async one 32KB level (2048 uint4) GMEM -> SMEM, 8 x 16B per thread
__device__ __forceinline__ void prefetch_level(const uint4* __restrict__ src,
                                               uint32_t dst, int tid) {
    #pragma unroll
    for (int i = 0; i < 8; ++i) {
        uint32_t d = dst + (uint32_t)(tid + i * NT) * 16u;
        const uint4* s = src + tid + i * NT;
        asm volatile("cp.async.cg.shared.global [%0], [%1], 16;"
                     :: "r"(d), "l"(s) : "memory");
    }
    asm volatile("cp.async.commit_group;" ::: "memory");
}
#define CP_WAIT0() asm volatile("cp.async.wait_group 0;" ::: "memory")

// ---------------------------------------------------------------------------
// Prep kernel: split W2/W3 of every branch into swizzled scaled-fp16 tiles
// ---------------------------------------------------------------------------
__global__ void prep_kernel(const float* __restrict__ W2,
                            const float* __restrict__ W3)
{
    int iter = blockIdx.x;          // 0..5
    int b = iter >> 1, l = iter & 1;
    const float* W = (l ? W3 : W2) + b * HD * HD;
    char* dst = (char*)g_Bsplit[iter];
    for (int g = threadIdx.x; g < 2048; g += blockDim.x) {
        int j = g >> 4;
        int kg = (g & 15) * 8;
        float4 w0 = *(const float4*)(W + j * HD + kg);
        float4 w1 = *(const float4*)(W + j * HD + kg + 4);
        uint4 h, lo;
        split2f_pair(w0.x, w0.y, h.x, lo.x);
        split2f_pair(w0.z, w0.w, h.y, lo.y);
        split2f_pair(w1.x, w1.y, h.z, lo.z);
        split2f_pair(w1.z, w1.w, h.w, lo.w);
        uint32_t ao = swz8(j, kg >> 3);
        *(uint4*)(dst + ao)         = h;
        *(uint4*)(dst + 32768 + ao) = lo;
    }
}

// ---------------------------------------------------------------------------
// Head kernel (known-good fp32): (v, dv) at n=0,1 for all branches
// ---------------------------------------------------------------------------
#define HWS 129
__global__ void head_kernel(const float* __restrict__ t,
    const float* __restrict__ W1, const float* __restrict__ b1,
    const float* __restrict__ W2, const float* __restrict__ b2,
    const float* __restrict__ W3, const float* __restrict__ b3,
    const float* __restrict__ W4, const float* __restrict__ b4)
{
    extern __shared__ float hsm[];
    __shared__ float2 A[HD], B[HD];
    __shared__ float2 red[HD];
    const int j = threadIdx.x;
    float tv0 = t[0], tv1 = t[1];

    for (int b = 0; b < 3; ++b) {
        float w1 = W1[b*HD + j];
        float c1 = b1[b*HD + j];
        float c2 = b2[b*HD + j];
        float c3 = b3[b*HD + j];
        float w4 = W4[b*HD + j];
        for (int n = 0; n < 2; ++n) {
            float tn = (n == 0) ? tv0 : tv1;
            float pre = fmaf(tn, w1, c1);
            A[j] = make_float2(fmaxf(pre, 0.f), pre > 0.f ? w1 : 0.f);
            __syncthreads();
            for (int idx = j; idx < HD*HD; idx += HD) {
                int jj = idx >> 7, k = idx & 127;
                hsm[jj*HWS + k] = W2[b*HD*HD + idx];
            }
            __syncthreads();
            {
                float av = 0.f, ad = 0.f;
                #pragma unroll 8
                for (int k = 0; k < HD; ++k) {
                    float w = hsm[j*HWS + k]; float2 h = A[k];
                    av = fmaf(w, h.x, av); ad = fmaf(w, h.y, ad);
                }
                float p = av + c2;
                B[j] = make_float2(fmaxf(p, 0.f), p > 0.f ? ad : 0.f);
            }
            __syncthreads();
            for (int idx = j; idx < HD*HD; idx += HD) {
                int jj = idx >> 7, k = idx & 127;
                hsm[jj*HWS + k] = W3[b*HD*HD + idx];
            }
            __syncthreads();
            {
                float av = 0.f, ad = 0.f;
                #pragma unroll 8
                for (int k = 0; k < HD; ++k) {
                    float w = hsm[j*HWS + k]; float2 h = B[k];
                    av = fmaf(w, h.x, av); ad = fmaf(w, h.y, ad);
                }
                float p = av + c3;
                A[j] = make_float2(fmaxf(p, 0.f), p > 0.f ? ad : 0.f);
            }
            __syncthreads();
            red[j] = make_float2(w4 * A[j].x, w4 * A[j].y);
            __syncthreads();
            for (int s = 64; s > 0; s >>= 1) {
                if (j < s) { red[j].x += red[j+s].x; red[j].y += red[j+s].y; }
                __syncthreads();
            }
            if (j == 0) g_head[b][n] = make_float2(red[0].x + b4[b], red[0].y);
            __syncthreads();
        }
    }
}

// ---------------------------------------------------------------------------
// Main kernel: 32 samples/CTA, 2 CTAs/SM for phase overlap. Value = 4-pass
// 2-level scaled-fp16 split; tangent = 2 passes. Full 64KB B resident.
// Per-warp work shape identical to the 1-CTA/SM version.
// ---------------------------------------------------------------------------
__global__ __launch_bounds__(NT, 2)
void main_kernel(const float* __restrict__ t,
    const float* __restrict__ W1, const float* __restrict__ b1,
    const float* __restrict__ b2, const float* __restrict__ b3,
    const float* __restrict__ W4, const float* __restrict__ b4,
    float* __restrict__ out, int N)
{
    extern __shared__ char smem_raw[];
    const uint32_t sb_raw = (uint32_t)__cvta_generic_to_shared(smem_raw);
    const uint32_t sb = (sb_raw + 1023u) & ~1023u;
    char* smA = smem_raw + (sb - sb_raw);

    const int tid  = threadIdx.x;
    const int lane = tid & 31;
    const int w    = tid >> 5;          // 0..7
    const int m0   = (w >> 2) * 16;     // warp's 16-row slab (M=32)
    const int wn   = w & 3;
    const int n0   = wn * 32;           // warp's 32-col slab

    float*  sW1 = (float*)(smA + OFF_MISC) + 0;
    float*  sC1 = (float*)(smA + OFF_MISC) + 128;
    float*  sB2 = (float*)(smA + OFF_MISC) + 256;
    float*  sB3 = (float*)(smA + OFF_MISC) + 384;
    float*  sW4 = (float*)(smA + OFF_MISC) + 512;
    float*  sT  = (float*)(smA + OFF_MISC) + 640;     // 32 floats
    float2* red = (float2*)(smA + OFF_MISC + 2816);   // [32][4]

    const int base = blockIdx.x * MT;
    if (tid < MT) sT[tid] = t[base + tid];

    const uint32_t AVH = sb + OFF_AVH, AVL = sb + OFF_AVL;
    const uint32_t ADH = sb + OFF_ADH;
    const uint32_t BH  = sb + OFF_BH,  BL  = sb + OFF_BL;

    // initial prefetch of iteration 0 (branch 0, W2)
    {
        const uint4* src = (const uint4*)g_Bsplit[0];
        prefetch_level(src,        BH, tid);
        prefetch_level(src + 2048, BL, tid);
    }

    for (int b = 0; b < 3; ++b) {
        if (tid < HD) {
            sW1[tid] = W1[b*HD + tid];
            sC1[tid] = b1[b*HD + tid];
            sB2[tid] = b2[b*HD + tid];
            sB3[tid] = b3[b*HD + tid];
            sW4[tid] = W4[b*HD + tid];
        }
        if (b == 0) CP_WAIT0();
        __syncthreads();

        // ---- layer 1: elementwise -> A split buffers (32 rows) ----
        #pragma unroll
        for (int i = 0; i < 2; ++i) {
            int g = tid + i * NT;          // 0..511
            int r = g >> 4, c0 = (g & 15) * 8;
            float tv = sT[r];
            float hv[8], hd[8];
            #pragma unroll
            for (int q = 0; q < 8; ++q) {
                float wv  = sW1[c0 + q];
                float pre = fmaf(tv, wv, sC1[c0 + q]);
                bool mk = pre > 0.f;
                hv[q] = mk ? pre : 0.f;
                hd[q] = mk ? wv  : 0.f;
            }
            uint4 vh, vl, dh;
            split2f_pair(hv[0], hv[1], vh.x, vl.x);
            split2f_pair(hv[2], hv[3], vh.y, vl.y);
            split2f_pair(hv[4], hv[5], vh.z, vl.z);
            split2f_pair(hv[6], hv[7], vh.w, vl.w);
            dh.x = pack_f16_pair(hd[0], hd[1]);
            dh.y = pack_f16_pair(hd[2], hd[3]);
            dh.z = pack_f16_pair(hd[4], hd[5]);
            dh.w = pack_f16_pair(hd[6], hd[7]);
            uint32_t ao = swz8(r, c0 >> 3);
            *(uint4*)(smA + OFF_AVH + ao) = vh;
            *(uint4*)(smA + OFF_AVL + ao) = vl;
            *(uint4*)(smA + OFF_ADH + ao) = dh;
        }
        __syncthreads();

        #pragma unroll 1
        for (int layer = 0; layer < 2; ++layer) {
            const int nxt = 2*b + layer + 1;    // next weight-set iteration

            float acc1[4][4], acc2[4][4], acc3[4][4], accd1[4][4], accd2[4][4];
            #pragma unroll
            for (int nt = 0; nt < 4; ++nt)
                #pragma unroll
                for (int q = 0; q < 4; ++q) {
                    acc1[nt][q]=0.f; acc2[nt][q]=0.f; acc3[nt][q]=0.f;
                    accd1[nt][q]=0.f; accd2[nt][q]=0.f;
                }

            // fused loop: 7 LDSM + 24 HMMA per ks
            #pragma unroll 1
            for (int ks = 0; ks < 8; ++ks) {
                const int ch = ks * 2;
                uint32_t avh[4], avl[4], adh[4];
                uint32_t bh[2][4], bl[2][4];
                ldmA(avh, AVH, m0, ch, lane);
                ldmA(avl, AVL, m0, ch, lane);
                ldmA(adh, ADH, m0, ch, lane);
                ldmB(bh[0], BH, n0, ch, lane); ldmB(bh[1], BH, n0 + 16, ch, lane);
                ldmB(bl[0], BL, n0, ch, lane); ldmB(bl[1], BL, n0 + 16, ch, lane);
                #pragma unroll
                for (int nt = 0; nt < 4; ++nt) {
                    uint32_t b0h = bh[nt>>1][(nt&1)*2], b1h = bh[nt>>1][(nt&1)*2+1];
                    uint32_t b0l = bl[nt>>1][(nt&1)*2], b1l = bl[nt>>1][(nt&1)*2+1];
                    mma_f16(acc1[nt],  avh, b0h, b1h);
                    mma_f16(accd1[nt], adh, b0h, b1h);
                    mma_f16(acc2[nt],  avl, b0h, b1h);
                    mma_f16(acc2[nt],  avh, b0l, b1l);
                    mma_f16(accd2[nt], adh, b0l, b1l);
                    mma_f16(acc3[nt],  avl, b0l, b1l);
                }
            }
            __syncthreads();      // all warps done reading A + B
            if (nxt < 6) {
                const uint4* src = (const uint4*)g_Bsplit[nxt];
                prefetch_level(src,        BH, tid);
                prefetch_level(src + 2048, BL, tid);
            }

            if (layer == 0) {
                // ---- epilogue 2: combine + bias + relu + resplit -> A ----
                float bb[8];
                #pragma unroll
                for (int nt = 0; nt < 4; ++nt) {
                    int c = n0 + 8*nt + (lane & 3)*2;
                    bb[2*nt] = sB2[c]; bb[2*nt+1] = sB2[c+1];
                }
                #pragma unroll
                for (int h = 0; h < 2; ++h) {
                    int row = m0 + 8*h + (lane >> 2);
                    #pragma unroll
                    for (int nt = 0; nt < 4; ++nt) {
                        int c = n0 + 8*nt + (lane & 3)*2;
                        float p0 = acc1[nt][2*h]   + fmaf(acc2[nt][2*h],   S_DN,
                                     fmaf(acc3[nt][2*h],   S_DN2, bb[2*nt]));
                        float p1 = acc1[nt][2*h+1] + fmaf(acc2[nt][2*h+1], S_DN,
                                     fmaf(acc3[nt][2*h+1], S_DN2, bb[2*nt+1]));
                        bool q0 = p0 > 0.f, q1 = p1 > 0.f;
                        float v0 = q0 ? p0 : 0.f, v1 = q1 ? p1 : 0.f;
                        float d0 = q0 ? fmaf(accd2[nt][2*h],   S_DN, accd1[nt][2*h])   : 0.f;
                        float d1 = q1 ? fmaf(accd2[nt][2*h+1], S_DN, accd1[nt][2*h+1]) : 0.f;
                        uint32_t vh, vl;
                        split2f_pair(v0, v1, vh, vl);
                        uint32_t dh = pack_f16_pair(d0, d1);
                        uint32_t ao = swz8(row, c >> 3) + ((c & 7) << 1);
                        *(uint32_t*)(smA + OFF_AVH + ao) = vh;
                        *(uint32_t*)(smA + OFF_AVL + ao) = vl;
                        *(uint32_t*)(smA + OFF_ADH + ao) = dh;
                    }
                }
                CP_WAIT0();
                __syncthreads();
            } else {
                // ---- epilogue 3: combine + bias + relu + dot(w4) + post ----
                float bb[8], ww[8];
                #pragma unroll
                for (int nt = 0; nt < 4; ++nt) {
                    int c = n0 + 8*nt + (lane & 3)*2;
                    bb[2*nt] = sB3[c]; bb[2*nt+1] = sB3[c+1];
                    ww[2*nt] = sW4[c]; ww[2*nt+1] = sW4[c+1];
                }
                #pragma unroll
                for (int h = 0; h < 2; ++h) {
                    int row = m0 + 8*h + (lane >> 2);
                    float sv = 0.f, sd = 0.f;
                    #pragma unroll
                    for (int nt = 0; nt < 4; ++nt) {
                        float p0 = acc1[nt][2*h]   + fmaf(acc2[nt][2*h],   S_DN,
                                     fmaf(acc3[nt][2*h],   S_DN2, bb[2*nt]));
                        float p1 = acc1[nt][2*h+1] + fmaf(acc2[nt][2*h+1], S_DN,
                                     fmaf(acc3[nt][2*h+1], S_DN2, bb[2*nt+1]));
                        bool q0 = p0 > 0.f, q1 = p1 > 0.f;
                        float d0 = fmaf(accd2[nt][2*h],   S_DN, accd1[nt][2*h]);
                        float d1 = fmaf(accd2[nt][2*h+1], S_DN, accd1[nt][2*h+1]);
                        sv = fmaf(q0 ? p0 : 0.f, ww[2*nt],   sv);
                        sv = fmaf(q1 ? p1 : 0.f, ww[2*nt+1], sv);
                        sd = fmaf(q0 ? d0 : 0.f, ww[2*nt],   sd);
                        sd = fmaf(q1 ? d1 : 0.f, ww[2*nt+1], sd);
                    }
                    sv += __shfl_xor_sync(0xffffffffu, sv, 1);
                    sv += __shfl_xor_sync(0xffffffffu, sv, 2);
                    sd += __shfl_xor_sync(0xffffffffu, sd, 1);
                    sd += __shfl_xor_sync(0xffffffffu, sd, 2);
                    if ((lane & 3) == 0) red[row*4 + wn] = make_float2(sv, sd);
                }
                CP_WAIT0();
                __syncthreads();

                if (tid < MT) {
                    float2 r0 = red[tid*4+0], r1 = red[tid*4+1],
                           r2 = red[tid*4+2], r3 = red[tid*4+3];
                    float v  = r0.x + r1.x + r2.x + r3.x + b4[b];
                    float dv = r0.y + r1.y + r2.y + r3.y;
                    float2 h0 = g_head[b][0];
                    float2 h1 = g_head[b][1];
                    float s = (b == 1) ? -1.f : 1.f;
                    float d1 = h1.x - h0.x;
                    float sg1 = (d1 > 0.f) ? 1.f : ((d1 < 0.f) ? -1.f : 0.f);
                    float dsign1 = s * sg1 * h1.y;
                    int n = base + tid;
                    float d = v - h0.x;
                    float vv, ds;
                    if (n == 0) {
                        vv = 0.f;
                        ds = (dsign1 >= 0.f) ? fabsf(dv) : -fabsf(dv);
                    } else {
                        float sg = (d > 0.f) ? 1.f : ((d < 0.f) ? -1.f : 0.f);
                        vv = s * fabsf(d);
                        ds = s * sg * dv;
                    }
                    out[b*N + n]       = vv;
                    out[(3 + b)*N + n] = ds;
                }
                __syncthreads();
            }
        }
    }
}

// ---------------------------------------------------------------------------
extern "C" void kernel_launch(void* const* d_in, const int* in_sizes, int n_in,
                              void* d_out, int out_size)
{
    const float* t  = (const float*)d_in[0];
    const float* W1 = (const float*)d_in[1];
    const float* b1 = (const float*)d_in[2];
    const float* W2 = (const float*)d_in[3];
    const float* b2 = (const float*)d_in[4];
    const float* W3 = (const float*)d_in[5];
    const float* b3 = (const float*)d_in[6];
    const float* W4 = (const float*)d_in[7];
    const float* b4 = (const float*)d_in[8];
    float* out = (float*)d_out;
    const int N = in_sizes[0];

    const int HEAD_SMEM = HD * HWS * 4;

    cudaFuncSetAttribute(main_kernel, cudaFuncAttributeMaxDynamicSharedMemorySize, MAIN_SMEM);
    cudaFuncSetAttribute(head_kernel, cudaFuncAttributeMaxDynamicSharedMemorySize, HEAD_SMEM);

    prep_kernel<<<6, 256>>>(W2, W3);
    head_kernel<<<1, HD, HEAD_SMEM>>>(t, W1, b1, W2, b2, W3, b3, W4, b4);
    main_kernel<<<N / MT, NT, MAIN_SMEM>>>(t, W1, b1, b2, b3, W4, b4, out, N);
}

// round 13
// speedup vs baseline: 1.9720x; 1.0269x over previous
#include <cuda_runtime.h>
#include <cuda_fp16.h>
#include <cstdint>

#define HD 128
#define NT 256
#define MTILE 32          // rows per tile; 2 tiles per CTA (64 samples)

// byte offsets in dynamic smem (base used as-is; swizzle is translation-invariant)
#define OFF_AVH0 0u
#define OFF_AVL0 8192u
#define OFF_ADH0 16384u
#define OFF_AVH1 24576u
#define OFF_AVL1 32768u
#define OFF_ADH1 40960u
#define OFF_BH   49152u
#define OFF_BL   81920u
#define MAIN_SMEM 114688

#define S_UP   2048.0f                  // 2^11
#define S_DN   4.8828125e-4f            // 2^-11
#define S_DN2  2.384185791015625e-7f    // 2^-22

__device__ float2 g_head[3][2];
// pre-split swizzled weight tiles per iteration (iter = 2*branch + layer):
// levels H/L each 8192 u32 (32KB)
__device__ uint32_t g_Bsplit[6][2 * 8192];

// ---------------------------------------------------------------------------
// scaled fp16 split helpers
// ---------------------------------------------------------------------------
__device__ __forceinline__ float f16_rn(float x, uint32_t& bits) {
    __half h = __float2half_rn(x);
    bits = (uint32_t)__half_as_ushort(h);
    return __half2float(h);
}
__device__ __forceinline__ uint32_t pack_f16_pair(float a, float b) {
    uint32_t r;
    asm("cvt.rn.f16x2.f32 %0, %1, %2;" : "=r"(r) : "f"(b), "f"(a));
    return r;
}
// x ≈ h + l*2^-11 with l stored scaled by 2^11 (residual ~2^-24)
__device__ __forceinline__ void split2f_pair(float a, float b,
                                             uint32_t& h, uint32_t& l) {
    uint32_t ha, la, hb, lb;
    float f = f16_rn(a, ha); f16_rn((a - f) * S_UP, la);
    f = f16_rn(b, hb);       f16_rn((b - f) * S_UP, lb);
    h = ha | (hb << 16); l = la | (lb << 16);
}

// swizzled byte offset inside a [rows x 128 f16] tile (row stride 256B)
__device__ __forceinline__ uint32_t swz8(int row, int col8) {
    return (uint32_t)(row * 256) + ((uint32_t)((col8 ^ (row & 7))) << 4);
}

// ---------------------------------------------------------------------------
// ldmatrix / mma wrappers (baseline PTX, compute_103-safe)
// ---------------------------------------------------------------------------
__device__ __forceinline__ void ldmA(uint32_t f[4], uint32_t base, int r0, int ch, int lane) {
    int g = lane >> 3, i = lane & 7;
    int row = r0 + i + ((g & 1) << 3);
    int c   = ch + (g >> 1);
    uint32_t addr = base + swz8(row, c);
    asm volatile("ldmatrix.sync.aligned.m8n8.x4.shared.b16 {%0,%1,%2,%3}, [%4];"
                 : "=r"(f[0]), "=r"(f[1]), "=r"(f[2]), "=r"(f[3]) : "r"(addr));
}
__device__ __forceinline__ void ldmB(uint32_t f[4], uint32_t base, int n0, int ch, int lane) {
    int g = lane >> 3, i = lane & 7;
    int row = n0 + i + ((g >> 1) << 3);
    int c   = ch + (g & 1);
    uint32_t addr = base + swz8(row, c);
    asm volatile("ldmatrix.sync.aligned.m8n8.x4.shared.b16 {%0,%1,%2,%3}, [%4];"
                 : "=r"(f[0]), "=r"(f[1]), "=r"(f[2]), "=r"(f[3]) : "r"(addr));
}
__device__ __forceinline__ void mma_f16(float c[4], const uint32_t a[4],
                                        uint32_t b0, uint32_t b1) {
    asm volatile("mma.sync.aligned.m16n8k16.row.col.f32.f16.f16.f32 "
                 "{%0,%1,%2,%3}, {%4,%5,%6,%7}, {%8,%9}, {%0,%1,%2,%3};"
                 : "+f"(c[0]), "+f"(c[1]), "+f"(c[2]), "+f"(c[3])
                 : "r"(a[0]), "r"(a[1]), "r"(a[2]), "r"(a[3]), "r"(b0), "r"(b1));
}

// cp.async one 32KB level (2048 uint4) GMEM -> SMEM, 8 x 16B per thread
__device__ __forceinline__ void prefetch_level(const uint4* __restrict__ src,
                                               uint32_t dst, int tid) {
    #pragma unroll
    for (int i = 0; i < 8; ++i) {
        uint32_t d = dst + (uint32_t)(tid + i * NT) * 16u;
        const uint4* s = src + tid + i * NT;
        asm volatile("cp.async.cg.shared.global [%0], [%1], 16;"
                     :: "r"(d), "l"(s) : "memory");
    }
    asm volatile("cp.async.commit_group;" ::: "memory");
}
#define CP_WAIT0() asm volatile("cp.async.wait_group 0;" ::: "memory")

// full 6-pass MMA over one 32-row tile (A bufs given), accumulating 5 acc sets
__device__ __forceinline__ void mma_tile(uint32_t AVH, uint32_t AVL, uint32_t ADH,
                                         uint32_t BH, uint32_t BL,
                                         int m0, int n0, int lane,
                                         float acc1[4][4], float acc2[4][4],
                                         float acc3[4][4], float accd1[4][4],
                                         float accd2[4][4])
{
    #pragma unroll
    for (int nt = 0; nt < 4; ++nt)
        #pragma unroll
        for (int q = 0; q < 4; ++q) {
            acc1[nt][q]=0.f; acc2[nt][q]=0.f; acc3[nt][q]=0.f;
            accd1[nt][q]=0.f; accd2[nt][q]=0.f;
        }
    #pragma unroll 1
    for (int ks = 0; ks < 8; ++ks) {
        const int ch = ks * 2;
        uint32_t avh[4], avl[4], adh[4];
        uint32_t bh[2][4], bl[2][4];
        ldmA(avh, AVH, m0, ch, lane);
        ldmA(avl, AVL, m0, ch, lane);
        ldmA(adh, ADH, m0, ch, lane);
        ldmB(bh[0], BH, n0, ch, lane); ldmB(bh[1], BH, n0 + 16, ch, lane);
        ldmB(bl[0], BL, n0, ch, lane); ldmB(bl[1], BL, n0 + 16, ch, lane);
        #pragma unroll
        for (int nt = 0; nt < 4; ++nt) {
            uint32_t b0h = bh[nt>>1][(nt&1)*2], b1h = bh[nt>>1][(nt&1)*2+1];
            uint32_t b0l = bl[nt>>1][(nt&1)*2], b1l = bl[nt>>1][(nt&1)*2+1];
            mma_f16(acc1[nt],  avh, b0h, b1h);
            mma_f16(accd1[nt], adh, b0h, b1h);
            mma_f16(acc2[nt],  avl, b0h, b1h);
            mma_f16(acc2[nt],  avh, b0l, b1l);
            mma_f16(accd2[nt], adh, b0l, b1l);
            mma_f16(acc3[nt],  avl, b0l, b1l);
        }
    }
}

// ---------------------------------------------------------------------------
// Prep kernel: split W2/W3 of every branch into swizzled scaled-fp16 tiles
// ---------------------------------------------------------------------------
__global__ void prep_kernel(const float* __restrict__ W2,
                            const float* __restrict__ W3)
{
    int iter = blockIdx.x;          // 0..5
    int b = iter >> 1, l = iter & 1;
    const float* W = (l ? W3 : W2) + b * HD * HD;
    char* dst = (char*)g_Bsplit[iter];
    for (int g = threadIdx.x; g < 2048; g += blockDim.x) {
        int j = g >> 4;
        int kg = (g & 15) * 8;
        float4 w0 = *(const float4*)(W + j * HD + kg);
        float4 w1 = *(const float4*)(W + j * HD + kg + 4);
        uint4 h, lo;
        split2f_pair(w0.x, w0.y, h.x, lo.x);
        split2f_pair(w0.z, w0.w, h.y, lo.y);
        split2f_pair(w1.x, w1.y, h.z, lo.z);
        split2f_pair(w1.z, w1.w, h.w, lo.w);
        uint32_t ao = swz8(j, kg >> 3);
        *(uint4*)(dst + ao)         = h;
        *(uint4*)(dst + 32768 + ao) = lo;
    }
}

// ---------------------------------------------------------------------------
// Head kernel (known-good fp32): (v, dv) at n=0,1 for all branches
// ---------------------------------------------------------------------------
#define HWS 129
__global__ void head_kernel(const float* __restrict__ t,
    const float* __restrict__ W1, const float* __restrict__ b1,
    const float* __restrict__ W2, const float* __restrict__ b2,
    const float* __restrict__ W3, const float* __restrict__ b3,
    const float* __restrict__ W4, const float* __restrict__ b4)
{
    extern __shared__ float hsm[];
    __shared__ float2 A[HD], B[HD];
    __shared__ float2 red[HD];
    const int j = threadIdx.x;
    float tv0 = t[0], tv1 = t[1];

    for (int b = 0; b < 3; ++b) {
        float w1 = W1[b*HD + j];
        float c1 = b1[b*HD + j];
        float c2 = b2[b*HD + j];
        float c3 = b3[b*HD + j];
        float w4 = W4[b*HD + j];
        for (int n = 0; n < 2; ++n) {
            float tn = (n == 0) ? tv0 : tv1;
            float pre = fmaf(tn, w1, c1);
            A[j] = make_float2(fmaxf(pre, 0.f), pre > 0.f ? w1 : 0.f);
            __syncthreads();
            for (int idx = j; idx < HD*HD; idx += HD) {
                int jj = idx >> 7, k = idx & 127;
                hsm[jj*HWS + k] = W2[b*HD*HD + idx];
            }
            __syncthreads();
            {
                float av = 0.f, ad = 0.f;
                #pragma unroll 8
                for (int k = 0; k < HD; ++k) {
                    float w = hsm[j*HWS + k]; float2 h = A[k];
                    av = fmaf(w, h.x, av); ad = fmaf(w, h.y, ad);
                }
                float p = av + c2;
                B[j] = make_float2(fmaxf(p, 0.f), p > 0.f ? ad : 0.f);
            }
            __syncthreads();
            for (int idx = j; idx < HD*HD; idx += HD) {
                int jj = idx >> 7, k = idx & 127;
                hsm[jj*HWS + k] = W3[b*HD*HD + idx];
            }
            __syncthreads();
            {
                float av = 0.f, ad = 0.f;
                #pragma unroll 8
                for (int k = 0; k < HD; ++k) {
                    float w = hsm[j*HWS + k]; float2 h = B[k];
                    av = fmaf(w, h.x, av); ad = fmaf(w, h.y, ad);
                }
                float p = av + c3;
                A[j] = make_float2(fmaxf(p, 0.f), p > 0.f ? ad : 0.f);
            }
            __syncthreads();
            red[j] = make_float2(w4 * A[j].x, w4 * A[j].y);
            __syncthreads();
            for (int s = 64; s > 0; s >>= 1) {
                if (j < s) { red[j].x += red[j+s].x; red[j].y += red[j+s].y; }
                __syncthreads();
            }
            if (j == 0) g_head[b][n] = make_float2(red[0].x + b4[b], red[0].y);
            __syncthreads();
        }
    }
}

// ---------------------------------------------------------------------------
// Main kernel: 64 samples/CTA as 2x32-row tiles sharing one staged B;
// 2 CTAs/SM. epi(t0) overlaps MMA(t1) via warp drift. Biases from GMEM.
// ---------------------------------------------------------------------------
__global__ __launch_bounds__(NT, 2)
void main_kernel(const float* __restrict__ t,
    const float* __restrict__ W1, const float* __restrict__ b1,
    const float* __restrict__ b2, const float* __restrict__ b3,
    const float* __restrict__ W4, const float* __restrict__ b4,
    float* __restrict__ out, int N)
{
    extern __shared__ char smA[];
    const uint32_t sb = (uint32_t)__cvta_generic_to_shared(smA);

    const int tid  = threadIdx.x;
    const int lane = tid & 31;
    const int w    = tid >> 5;          // 0..7
    const int m0   = (w >> 2) * 16;     // row slab within a 32-row tile
    const int wn   = w & 3;
    const int n0   = wn * 32;           // 32-col slab

    const int base = blockIdx.x * (2 * MTILE);

    const uint32_t AVH[2] = {sb + OFF_AVH0, sb + OFF_AVH1};
    const uint32_t AVL[2] = {sb + OFF_AVL0, sb + OFF_AVL1};
    const uint32_t ADH[2] = {sb + OFF_ADH0, sb + OFF_ADH1};
    const uint32_t BH = sb + OFF_BH, BL = sb + OFF_BL;
    float2* red0 = (float2*)(smA + OFF_ADH0);   // alias: dead after last MMA(t0)
    float2* red1 = (float2*)(smA + OFF_ADH1);

    // initial prefetch of iteration 0 (branch 0, W2)
    {
        const uint4* src = (const uint4*)g_Bsplit[0];
        prefetch_level(src,        BH, tid);
        prefetch_level(src + 2048, BL, tid);
    }

    for (int b = 0; b < 3; ++b) {
        __syncthreads();    // guards red reads of prev branch vs A overwrite

        // ---- layer 1 (both tiles): elementwise -> A split buffers ----
        #pragma unroll
        for (int i = 0; i < 4; ++i) {
            int g = tid + i * NT;             // 0..1023
            int tile = g >> 9;
            int gg = g & 511;
            int r = gg >> 4, c0 = (gg & 15) * 8;
            float tv = __ldg(t + base + tile * MTILE + r);
            float4 w1a = __ldg((const float4*)(W1 + b*HD + c0));
            float4 w1b = __ldg((const float4*)(W1 + b*HD + c0 + 4));
            float4 c1a = __ldg((const float4*)(b1 + b*HD + c0));
            float4 c1b = __ldg((const float4*)(b1 + b*HD + c0 + 4));
            float wv[8] = {w1a.x,w1a.y,w1a.z,w1a.w,w1b.x,w1b.y,w1b.z,w1b.w};
            float cv[8] = {c1a.x,c1a.y,c1a.z,c1a.w,c1b.x,c1b.y,c1b.z,c1b.w};
            float hv[8], hd[8];
            #pragma unroll
            for (int q = 0; q < 8; ++q) {
                float pre = fmaf(tv, wv[q], cv[q]);
                bool mk = pre > 0.f;
                hv[q] = mk ? pre : 0.f;
                hd[q] = mk ? wv[q] : 0.f;
            }
            uint4 vh, vl, dh;
            split2f_pair(hv[0], hv[1], vh.x, vl.x);
            split2f_pair(hv[2], hv[3], vh.y, vl.y);
            split2f_pair(hv[4], hv[5], vh.z, vl.z);
            split2f_pair(hv[6], hv[7], vh.w, vl.w);
            dh.x = pack_f16_pair(hd[0], hd[1]);
            dh.y = pack_f16_pair(hd[2], hd[3]);
            dh.z = pack_f16_pair(hd[4], hd[5]);
            dh.w = pack_f16_pair(hd[6], hd[7]);
            uint32_t ao = swz8(r, c0 >> 3);
            *(uint4*)(smA + (tile ? OFF_AVH1 : OFF_AVH0) + ao) = vh;
            *(uint4*)(smA + (tile ? OFF_AVL1 : OFF_AVL0) + ao) = vl;
            *(uint4*)(smA + (tile ? OFF_ADH1 : OFF_ADH0) + ao) = dh;
        }
        if (b == 0) CP_WAIT0();
        __syncthreads();

        #pragma unroll 1
        for (int layer = 0; layer < 2; ++layer) {
            const int nxt = 2*b + layer + 1;
            const float* bias = (layer == 0) ? b2 : b3;

            float acc1[4][4], acc2[4][4], acc3[4][4], accd1[4][4], accd2[4][4];

            #pragma unroll 1
            for (int tile = 0; tile < 2; ++tile) {
                mma_tile(AVH[tile], AVL[tile], ADH[tile], BH, BL,
                         m0, n0, lane, acc1, acc2, acc3, accd1, accd2);
                __syncthreads();   // A[tile] readers done (and, for tile1, B done)

                if (tile == 1 && nxt < 6) {
                    const uint4* src = (const uint4*)g_Bsplit[nxt];
                    prefetch_level(src,        BH, tid);
                    prefetch_level(src + 2048, BL, tid);
                }
                if (tile == 1 && layer == 1 && tid < MTILE) {
                    // out writes for tile 0 (red0 complete since the sync)
                    float2 r0 = red0[tid*4+0], r1 = red0[tid*4+1],
                           r2 = red0[tid*4+2], r3 = red0[tid*4+3];
                    float v  = r0.x + r1.x + r2.x + r3.x + __ldg(b4 + b);
                    float dv = r0.y + r1.y + r2.y + r3.y;
                    float2 h0 = g_head[b][0];
                    float2 h1 = g_head[b][1];
                    float s = (b == 1) ? -1.f : 1.f;
                    float d1 = h1.x - h0.x;
                    float sg1 = (d1 > 0.f) ? 1.f : ((d1 < 0.f) ? -1.f : 0.f);
                    float dsign1 = s * sg1 * h1.y;
                    int n = base + tid;
                    float d = v - h0.x;
                    float vv, ds;
                    if (n == 0) {
                        vv = 0.f;
                        ds = (dsign1 >= 0.f) ? fabsf(dv) : -fabsf(dv);
                    } else {
                        float sg = (d > 0.f) ? 1.f : ((d < 0.f) ? -1.f : 0.f);
                        vv = s * fabsf(d);
                        ds = s * sg * dv;
                    }
                    out[b*N + n]       = vv;
                    out[(3 + b)*N + n] = ds;
                }

                if (layer == 0) {
                    // ---- epilogue 2: combine + bias + relu + resplit ----
                    #pragma unroll
                    for (int h = 0; h < 2; ++h) {
                        int row = m0 + 8*h + (lane >> 2);
                        #pragma unroll
                        for (int nt = 0; nt < 4; ++nt) {
                            int c = n0 + 8*nt + (lane & 3)*2;
                            float2 bb = __ldg((const float2*)(bias + b*HD + c));
                            float p0 = acc1[nt][2*h]   + fmaf(acc2[nt][2*h],   S_DN,
                                         fmaf(acc3[nt][2*h],   S_DN2, bb.x));
                            float p1 = acc1[nt][2*h+1] + fmaf(acc2[nt][2*h+1], S_DN,
                                         fmaf(acc3[nt][2*h+1], S_DN2, bb.y));
                            bool q0 = p0 > 0.f, q1 = p1 > 0.f;
                            float v0 = q0 ? p0 : 0.f, v1 = q1 ? p1 : 0.f;
                            float d0 = q0 ? fmaf(accd2[nt][2*h],   S_DN, accd1[nt][2*h])   : 0.f;
                            float d1 = q1 ? fmaf(accd2[nt][2*h+1], S_DN, accd1[nt][2*h+1]) : 0.f;
                            uint32_t vh, vl;
                            split2f_pair(v0, v1, vh, vl);
                            uint32_t dh = pack_f16_pair(d0, d1);
                            uint32_t ao = swz8(row, c >> 3) + ((c & 7) << 1);
                            *(uint32_t*)(smA + (tile ? OFF_AVH1 : OFF_AVH0) + ao) = vh;
                            *(uint32_t*)(smA + (tile ? OFF_AVL1 : OFF_AVL0) + ao) = vl;
                            *(uint32_t*)(smA + (tile ? OFF_ADH1 : OFF_ADH0) + ao) = dh;
                        }
                    }
                } else {
                    // ---- epilogue 3: combine + bias + relu + dot(w4) ----
                    float2* red = tile ? red1 : red0;
                    #pragma unroll
                    for (int h = 0; h < 2; ++h) {
                        int row = m0 + 8*h + (lane >> 2);
                        float sv = 0.f, sd = 0.f;
                        #pragma unroll
                        for (int nt = 0; nt < 4; ++nt) {
                            int c = n0 + 8*nt + (lane & 3)*2;
                            float2 bb = __ldg((const float2*)(b3 + b*HD + c));
                            float2 ww = __ldg((const float2*)(W4 + b*HD + c));
                            float p0 = acc1[nt][2*h]   + fmaf(acc2[nt][2*h],   S_DN,
                                         fmaf(acc3[nt][2*h],   S_DN2, bb.x));
                            float p1 = acc1[nt][2*h+1] + fmaf(acc2[nt][2*h+1], S_DN,
                                         fmaf(acc3[nt][2*h+1], S_DN2, bb.y));
                            bool q0 = p0 > 0.f, q1 = p1 > 0.f;
                            float d0 = fmaf(accd2[nt][2*h],   S_DN, accd1[nt][2*h]);
                            float d1 = fmaf(accd2[nt][2*h+1], S_DN, accd1[nt][2*h+1]);
                            sv = fmaf(q0 ? p0 : 0.f, ww.x, sv);
                            sv = fmaf(q1 ? p1 : 0.f, ww.y, sv);
                            sd = fmaf(q0 ? d0 : 0.f, ww.x, sd);
                            sd = fmaf(q1 ? d1 : 0.f, ww.y, sd);
                        }
                        sv += __shfl_xor_sync(0xffffffffu, sv, 1);
                        sv += __shfl_xor_sync(0xffffffffu, sv, 2);
                        sd += __shfl_xor_sync(0xffffffffu, sd, 1);
                        sd += __shfl_xor_sync(0xffffffffu, sd, 2);
                        if ((lane & 3) == 0) red[row*4 + wn] = make_float2(sv, sd);
                    }
                }

                if (tile == 1) {
                    CP_WAIT0();
                }
            }
            __syncthreads();   // A' writes + red1 + next B all in place

            if (layer == 1 && tid < MTILE) {
                // out writes for tile 1
                float2 r0 = red1[tid*4+0], r1 = red1[tid*4+1],
                       r2 = red1[tid*4+2], r3 = red1[tid*4+3];
                float v  = r0.x + r1.x + r2.x + r3.x + __ldg(b4 + b);
                float dv = r0.y + r1.y + r2.y + r3.y;
                float2 h0 = g_head[b][0];
                float2 h1 = g_head[b][1];
                float s = (b == 1) ? -1.f : 1.f;
                float d1 = h1.x - h0.x;
                float sg1 = (d1 > 0.f) ? 1.f : ((d1 < 0.f) ? -1.f : 0.f);
                float dsign1 = s * sg1 * h1.y;
                int n = base + MTILE + tid;
                float d = v - h0.x;
                float vv, ds;
                if (n == 0) {
                    vv = 0.f;
                    ds = (dsign1 >= 0.f) ? fabsf(dv) : -fabsf(dv);
                } else {
                    float sg = (d > 0.f) ? 1.f : ((d < 0.f) ? -1.f : 0.f);
                    vv = s * fabsf(d);
                    ds = s * sg * dv;
                }
                out[b*N + n]       = vv;
                out[(3 + b)*N + n] = ds;
            }
        }
    }
}

// ---------------------------------------------------------------------------
extern "C" void kernel_launch(void* const* d_in, const int* in_sizes, int n_in,
                              void* d_out, int out_size)
{
    const float* t  = (const float*)d_in[0];
    const float* W1 = (const float*)d_in[1];
    const float* b1 = (const float*)d_in[2];
    const float* W2 = (const float*)d_in[3];
    const float* b2 = (const float*)d_in[4];
    const float* W3 = (const float*)d_in[5];
    const float* b3 = (const float*)d_in[6];
    const float* W4 = (const float*)d_in[7];
    const float* b4 = (const float*)d_in[8];
    float* out = (float*)d_out;
    const int N = in_sizes[0];

    const int HEAD_SMEM = HD * HWS * 4;

    cudaFuncSetAttribute(main_kernel, cudaFuncAttributeMaxDynamicSharedMemorySize, MAIN_SMEM);
    cudaFuncSetAttribute(head_kernel, cudaFuncAttributeMaxDynamicSharedMemorySize, HEAD_SMEM);

    prep_kernel<<<6, 256>>>(W2, W3);
    head_kernel<<<1, HD, HEAD_SMEM>>>(t, W1, b1, W2, b2, W3, b3, W4, b4);
    main_kernel<<<N / (2 * MTILE), NT, MAIN_SMEM>>>(t, W1, b1, b2, b3, W4, b4, out, N);
}

// round 14
// speedup vs baseline: 2.1808x; 1.1059x over previous
#include <cuda_runtime.h>
#include <cuda_fp16.h>
#include <cstdint>

#define HD 128
#define NT 256
#define MTILE 32          // rows per tile; 2 tiles per CTA (64 samples)

// byte offsets in dynamic smem (base used as-is; swizzle is translation-invariant)
#define OFF_AVH0 0u
#define OFF_AVL0 8192u
#define OFF_ADH0 16384u
#define OFF_AVH1 24576u
#define OFF_AVL1 32768u
#define OFF_ADH1 40960u
#define OFF_BH   49152u
#define OFF_BL   81920u
#define MAIN_SMEM 114688

#define S_UP   2048.0f                  // 2^11
#define S_DN   4.8828125e-4f            // 2^-11
#define S_DN2  2.384185791015625e-7f    // 2^-22

__device__ float2 g_head[3][2];
// pre-split swizzled weight tiles per iteration (iter = 2*branch + layer):
// levels H/L each 8192 u32 (32KB)
__device__ uint32_t g_Bsplit[6][2 * 8192];

// ---------------------------------------------------------------------------
// scaled fp16 split helpers
// ---------------------------------------------------------------------------
__device__ __forceinline__ float f16_rn(float x, uint32_t& bits) {
    __half h = __float2half_rn(x);
    bits = (uint32_t)__half_as_ushort(h);
    return __half2float(h);
}
__device__ __forceinline__ uint32_t pack_f16_pair(float a, float b) {
    uint32_t r;
    asm("cvt.rn.f16x2.f32 %0, %1, %2;" : "=r"(r) : "f"(b), "f"(a));
    return r;
}
// x ≈ h + l*2^-11 with l stored scaled by 2^11 (residual ~2^-24)
__device__ __forceinline__ void split2f_pair(float a, float b,
                                             uint32_t& h, uint32_t& l) {
    uint32_t ha, la, hb, lb;
    float f = f16_rn(a, ha); f16_rn((a - f) * S_UP, la);
    f = f16_rn(b, hb);       f16_rn((b - f) * S_UP, lb);
    h = ha | (hb << 16); l = la | (lb << 16);
}

// swizzled byte offset inside a [rows x 128 f16] tile (row stride 256B)
__device__ __forceinline__ uint32_t swz8(int row, int col8) {
    return (uint32_t)(row * 256) + ((uint32_t)((col8 ^ (row & 7))) << 4);
}

// ---------------------------------------------------------------------------
// ldmatrix / mma wrappers (baseline PTX, compute_103-safe)
// ---------------------------------------------------------------------------
__device__ __forceinline__ void ldmA(uint32_t f[4], uint32_t base, int r0, int ch, int lane) {
    int g = lane >> 3, i = lane & 7;
    int row = r0 + i + ((g & 1) << 3);
    int c   = ch + (g >> 1);
    uint32_t addr = base + swz8(row, c);
    asm volatile("ldmatrix.sync.aligned.m8n8.x4.shared.b16 {%0,%1,%2,%3}, [%4];"
                 : "=r"(f[0]), "=r"(f[1]), "=r"(f[2]), "=r"(f[3]) : "r"(addr));
}
__device__ __forceinline__ void ldmB(uint32_t f[4], uint32_t base, int n0, int ch, int lane) {
    int g = lane >> 3, i = lane & 7;
    int row = n0 + i + ((g >> 1) << 3);
    int c   = ch + (g & 1);
    uint32_t addr = base + swz8(row, c);
    asm volatile("ldmatrix.sync.aligned.m8n8.x4.shared.b16 {%0,%1,%2,%3}, [%4];"
                 : "=r"(f[0]), "=r"(f[1]), "=r"(f[2]), "=r"(f[3]) : "r"(addr));
}
__device__ __forceinline__ void mma_f16(float c[4], const uint32_t a[4],
                                        uint32_t b0, uint32_t b1) {
    asm volatile("mma.sync.aligned.m16n8k16.row.col.f32.f16.f16.f32 "
                 "{%0,%1,%2,%3}, {%4,%5,%6,%7}, {%8,%9}, {%0,%1,%2,%3};"
                 : "+f"(c[0]), "+f"(c[1]), "+f"(c[2]), "+f"(c[3])
                 : "r"(a[0]), "r"(a[1]), "r"(a[2]), "r"(a[3]), "r"(b0), "r"(b1));
}

// cp.async one 32KB level (2048 uint4) GMEM -> SMEM, 8 x 16B per thread
__device__ __forceinline__ void prefetch_level(const uint4* __restrict__ src,
                                               uint32_t dst, int tid) {
    #pragma unroll
    for (int i = 0; i < 8; ++i) {
        uint32_t d = dst + (uint32_t)(tid + i * NT) * 16u;
        const uint4* s = src + tid + i * NT;
        asm volatile("cp.async.cg.shared.global [%0], [%1], 16;"
                     :: "r"(d), "l"(s) : "memory");
    }
    asm volatile("cp.async.commit_group;" ::: "memory");
}
#define CP_WAIT0() asm volatile("cp.async.wait_group 0;" ::: "memory")

// 5-pass MMA over one 32-row tile: value 4 passes (hh, hl+lh, ll),
// tangent 1 pass (d·W_h, fp16-rounded weights).
__device__ __forceinline__ void mma_tile(uint32_t AVH, uint32_t AVL, uint32_t ADH,
                                         uint32_t BH, uint32_t BL,
                                         int m0, int n0, int lane,
                                         float acc1[4][4], float acc2[4][4],
                                         float acc3[4][4], float accd1[4][4])
{
    #pragma unroll
    for (int nt = 0; nt < 4; ++nt)
        #pragma unroll
        for (int q = 0; q < 4; ++q) {
            acc1[nt][q]=0.f; acc2[nt][q]=0.f; acc3[nt][q]=0.f;
            accd1[nt][q]=0.f;
        }
    #pragma unroll 1
    for (int ks = 0; ks < 8; ++ks) {
        const int ch = ks * 2;
        uint32_t avh[4], avl[4], adh[4];
        uint32_t bh[2][4], bl[2][4];
        ldmA(avh, AVH, m0, ch, lane);
        ldmA(avl, AVL, m0, ch, lane);
        ldmA(adh, ADH, m0, ch, lane);
        ldmB(bh[0], BH, n0, ch, lane); ldmB(bh[1], BH, n0 + 16, ch, lane);
        ldmB(bl[0], BL, n0, ch, lane); ldmB(bl[1], BL, n0 + 16, ch, lane);
        #pragma unroll
        for (int nt = 0; nt < 4; ++nt) {
            uint32_t b0h = bh[nt>>1][(nt&1)*2], b1h = bh[nt>>1][(nt&1)*2+1];
            uint32_t b0l = bl[nt>>1][(nt&1)*2], b1l = bl[nt>>1][(nt&1)*2+1];
            mma_f16(acc1[nt],  avh, b0h, b1h);
            mma_f16(accd1[nt], adh, b0h, b1h);
            mma_f16(acc2[nt],  avl, b0h, b1h);
            mma_f16(acc2[nt],  avh, b0l, b1l);
            mma_f16(acc3[nt],  avl, b0l, b1l);
        }
    }
}

// ---------------------------------------------------------------------------
// Prep kernel: split W2/W3 of every branch into swizzled scaled-fp16 tiles
// ---------------------------------------------------------------------------
__global__ void prep_kernel(const float* __restrict__ W2,
                            const float* __restrict__ W3)
{
    int iter = blockIdx.x;          // 0..5
    int b = iter >> 1, l = iter & 1;
    const float* W = (l ? W3 : W2) + b * HD * HD;
    char* dst = (char*)g_Bsplit[iter];
    for (int g = threadIdx.x; g < 2048; g += blockDim.x) {
        int j = g >> 4;
        int kg = (g & 15) * 8;
        float4 w0 = *(const float4*)(W + j * HD + kg);
        float4 w1 = *(const float4*)(W + j * HD + kg + 4);
        uint4 h, lo;
        split2f_pair(w0.x, w0.y, h.x, lo.x);
        split2f_pair(w0.z, w0.w, h.y, lo.y);
        split2f_pair(w1.x, w1.y, h.z, lo.z);
        split2f_pair(w1.z, w1.w, h.w, lo.w);
        uint32_t ao = swz8(j, kg >> 3);
        *(uint4*)(dst + ao)         = h;
        *(uint4*)(dst + 32768 + ao) = lo;
    }
}

// ---------------------------------------------------------------------------
// Head kernel (known-good fp32): (v, dv) at n=0,1 for all branches
// ---------------------------------------------------------------------------
#define HWS 129
__global__ void head_kernel(const float* __restrict__ t,
    const float* __restrict__ W1, const float* __restrict__ b1,
    const float* __restrict__ W2, const float* __restrict__ b2,
    const float* __restrict__ W3, const float* __restrict__ b3,
    const float* __restrict__ W4, const float* __restrict__ b4)
{
    extern __shared__ float hsm[];
    __shared__ float2 A[HD], B[HD];
    __shared__ float2 red[HD];
    const int j = threadIdx.x;
    float tv0 = t[0], tv1 = t[1];

    for (int b = 0; b < 3; ++b) {
        float w1 = W1[b*HD + j];
        float c1 = b1[b*HD + j];
        float c2 = b2[b*HD + j];
        float c3 = b3[b*HD + j];
        float w4 = W4[b*HD + j];
        for (int n = 0; n < 2; ++n) {
            float tn = (n == 0) ? tv0 : tv1;
            float pre = fmaf(tn, w1, c1);
            A[j] = make_float2(fmaxf(pre, 0.f), pre > 0.f ? w1 : 0.f);
            __syncthreads();
            for (int idx = j; idx < HD*HD; idx += HD) {
                int jj = idx >> 7, k = idx & 127;
                hsm[jj*HWS + k] = W2[b*HD*HD + idx];
            }
            __syncthreads();
            {
                float av = 0.f, ad = 0.f;
                #pragma unroll 8
                for (int k = 0; k < HD; ++k) {
                    float w = hsm[j*HWS + k]; float2 h = A[k];
                    av = fmaf(w, h.x, av); ad = fmaf(w, h.y, ad);
                }
                float p = av + c2;
                B[j] = make_float2(fmaxf(p, 0.f), p > 0.f ? ad : 0.f);
            }
            __syncthreads();
            for (int idx = j; idx < HD*HD; idx += HD) {
                int jj = idx >> 7, k = idx & 127;
                hsm[jj*HWS + k] = W3[b*HD*HD + idx];
            }
            __syncthreads();
            {
                float av = 0.f, ad = 0.f;
                #pragma unroll 8
                for (int k = 0; k < HD; ++k) {
                    float w = hsm[j*HWS + k]; float2 h = B[k];
                    av = fmaf(w, h.x, av); ad = fmaf(w, h.y, ad);
                }
                float p = av + c3;
                A[j] = make_float2(fmaxf(p, 0.f), p > 0.f ? ad : 0.f);
            }
            __syncthreads();
            red[j] = make_float2(w4 * A[j].x, w4 * A[j].y);
            __syncthreads();
            for (int s = 64; s > 0; s >>= 1) {
                if (j < s) { red[j].x += red[j+s].x; red[j].y += red[j+s].y; }
                __syncthreads();
            }
            if (j == 0) g_head[b][n] = make_float2(red[0].x + b4[b], red[0].y);
            __syncthreads();
        }
    }
}

// ---------------------------------------------------------------------------
// Main kernel: 64 samples/CTA as 2x32-row tiles sharing one staged B;
// 2 CTAs/SM. Value = 4-pass split GEMM; tangent = 1 pass vs W_h.
// ---------------------------------------------------------------------------
__global__ __launch_bounds__(NT, 2)
void main_kernel(const float* __restrict__ t,
    const float* __restrict__ W1, const float* __restrict__ b1,
    const float* __restrict__ b2, const float* __restrict__ b3,
    const float* __restrict__ W4, const float* __restrict__ b4,
    float* __restrict__ out, int N)
{
    extern __shared__ char smA[];
    const uint32_t sb = (uint32_t)__cvta_generic_to_shared(smA);

    const int tid  = threadIdx.x;
    const int lane = tid & 31;
    const int w    = tid >> 5;          // 0..7
    const int m0   = (w >> 2) * 16;     // row slab within a 32-row tile
    const int wn   = w & 3;
    const int n0   = wn * 32;           // 32-col slab

    const int base = blockIdx.x * (2 * MTILE);

    const uint32_t AVH[2] = {sb + OFF_AVH0, sb + OFF_AVH1};
    const uint32_t AVL[2] = {sb + OFF_AVL0, sb + OFF_AVL1};
    const uint32_t ADH[2] = {sb + OFF_ADH0, sb + OFF_ADH1};
    const uint32_t BH = sb + OFF_BH, BL = sb + OFF_BL;
    float2* red0 = (float2*)(smA + OFF_ADH0);   // alias: dead after last MMA(t0)
    float2* red1 = (float2*)(smA + OFF_ADH1);

    // initial prefetch of iteration 0 (branch 0, W2)
    {
        const uint4* src = (const uint4*)g_Bsplit[0];
        prefetch_level(src,        BH, tid);
        prefetch_level(src + 2048, BL, tid);
    }

    for (int b = 0; b < 3; ++b) {
        __syncthreads();    // guards red reads of prev branch vs A overwrite

        // ---- layer 1 (both tiles): elementwise -> A split buffers ----
        #pragma unroll
        for (int i = 0; i < 4; ++i) {
            int g = tid + i * NT;             // 0..1023
            int tile = g >> 9;
            int gg = g & 511;
            int r = gg >> 4, c0 = (gg & 15) * 8;
            float tv = __ldg(t + base + tile * MTILE + r);
            float4 w1a = __ldg((const float4*)(W1 + b*HD + c0));
            float4 w1b = __ldg((const float4*)(W1 + b*HD + c0 + 4));
            float4 c1a = __ldg((const float4*)(b1 + b*HD + c0));
            float4 c1b = __ldg((const float4*)(b1 + b*HD + c0 + 4));
            float wv[8] = {w1a.x,w1a.y,w1a.z,w1a.w,w1b.x,w1b.y,w1b.z,w1b.w};
            float cv[8] = {c1a.x,c1a.y,c1a.z,c1a.w,c1b.x,c1b.y,c1b.z,c1b.w};
            float hv[8], hd[8];
            #pragma unroll
            for (int q = 0; q < 8; ++q) {
                float pre = fmaf(tv, wv[q], cv[q]);
                bool mk = pre > 0.f;
                hv[q] = mk ? pre : 0.f;
                hd[q] = mk ? wv[q] : 0.f;
            }
            uint4 vh, vl, dh;
            split2f_pair(hv[0], hv[1], vh.x, vl.x);
            split2f_pair(hv[2], hv[3], vh.y, vl.y);
            split2f_pair(hv[4], hv[5], vh.z, vl.z);
            split2f_pair(hv[6], hv[7], vh.w, vl.w);
            dh.x = pack_f16_pair(hd[0], hd[1]);
            dh.y = pack_f16_pair(hd[2], hd[3]);
            dh.z = pack_f16_pair(hd[4], hd[5]);
            dh.w = pack_f16_pair(hd[6], hd[7]);
            uint32_t ao = swz8(r, c0 >> 3);
            *(uint4*)(smA + (tile ? OFF_AVH1 : OFF_AVH0) + ao) = vh;
            *(uint4*)(smA + (tile ? OFF_AVL1 : OFF_AVL0) + ao) = vl;
            *(uint4*)(smA + (tile ? OFF_ADH1 : OFF_ADH0) + ao) = dh;
        }
        if (b == 0) CP_WAIT0();
        __syncthreads();

        #pragma unroll 1
        for (int layer = 0; layer < 2; ++layer) {
            const int nxt = 2*b + layer + 1;
            const float* bias = (layer == 0) ? b2 : b3;

            float acc1[4][4], acc2[4][4], acc3[4][4], accd1[4][4];

            #pragma unroll 1
            for (int tile = 0; tile < 2; ++tile) {
                mma_tile(AVH[tile], AVL[tile], ADH[tile], BH, BL,
                         m0, n0, lane, acc1, acc2, acc3, accd1);
                __syncthreads();   // A[tile] readers done (and, for tile1, B done)

                if (tile == 1 && nxt < 6) {
                    const uint4* src = (const uint4*)g_Bsplit[nxt];
                    prefetch_level(src,        BH, tid);
                    prefetch_level(src + 2048, BL, tid);
                }
                if (tile == 1 && layer == 1 && tid < MTILE) {
                    // out writes for tile 0 (red0 complete since the sync)
                    float2 r0 = red0[tid*4+0], r1 = red0[tid*4+1],
                           r2 = red0[tid*4+2], r3 = red0[tid*4+3];
                    float v  = r0.x + r1.x + r2.x + r3.x + __ldg(b4 + b);
                    float dv = r0.y + r1.y + r2.y + r3.y;
                    float2 h0 = g_head[b][0];
                    float2 h1 = g_head[b][1];
                    float s = (b == 1) ? -1.f : 1.f;
                    float d1 = h1.x - h0.x;
                    float sg1 = (d1 > 0.f) ? 1.f : ((d1 < 0.f) ? -1.f : 0.f);
                    float dsign1 = s * sg1 * h1.y;
                    int n = base + tid;
                    float d = v - h0.x;
                    float vv, ds;
                    if (n == 0) {
                        vv = 0.f;
                        ds = (dsign1 >= 0.f) ? fabsf(dv) : -fabsf(dv);
                    } else {
                        float sg = (d > 0.f) ? 1.f : ((d < 0.f) ? -1.f : 0.f);
                        vv = s * fabsf(d);
                        ds = s * sg * dv;
                    }
                    out[b*N + n]       = vv;
                    out[(3 + b)*N + n] = ds;
                }

                if (layer == 0) {
                    // ---- epilogue 2: combine + bias + relu + resplit ----
                    #pragma unroll
                    for (int h = 0; h < 2; ++h) {
                        int row = m0 + 8*h + (lane >> 2);
                        #pragma unroll
                        for (int nt = 0; nt < 4; ++nt) {
                            int c = n0 + 8*nt + (lane & 3)*2;
                            float2 bb = __ldg((const float2*)(bias + b*HD + c));
                            float p0 = acc1[nt][2*h]   + fmaf(acc2[nt][2*h],   S_DN,
                                         fmaf(acc3[nt][2*h],   S_DN2, bb.x));
                            float p1 = acc1[nt][2*h+1] + fmaf(acc2[nt][2*h+1], S_DN,
                                         fmaf(acc3[nt][2*h+1], S_DN2, bb.y));
                            bool q0 = p0 > 0.f, q1 = p1 > 0.f;
                            float v0 = q0 ? p0 : 0.f, v1 = q1 ? p1 : 0.f;
                            float d0 = q0 ? accd1[nt][2*h]   : 0.f;
                            float d1 = q1 ? accd1[nt][2*h+1] : 0.f;
                            uint32_t vh, vl;
                            split2f_pair(v0, v1, vh, vl);
                            uint32_t dh = pack_f16_pair(d0, d1);
                            uint32_t ao = swz8(row, c >> 3) + ((c & 7) << 1);
                            *(uint32_t*)(smA + (tile ? OFF_AVH1 : OFF_AVH0) + ao) = vh;
                            *(uint32_t*)(smA + (tile ? OFF_AVL1 : OFF_AVL0) + ao) = vl;
                            *(uint32_t*)(smA + (tile ? OFF_ADH1 : OFF_ADH0) + ao) = dh;
                        }
                    }
                } else {
                    // ---- epilogue 3: combine + bias + relu + dot(w4) ----
                    float2* red = tile ? red1 : red0;
                    #pragma unroll
                    for (int h = 0; h < 2; ++h) {
                        int row = m0 + 8*h + (lane >> 2);
                        float sv = 0.f, sd = 0.f;
                        #pragma unroll
                        for (int nt = 0; nt < 4; ++nt) {
                            int c = n0 + 8*nt + (lane & 3)*2;
                            float2 bb = __ldg((const float2*)(b3 + b*HD + c));
                            float2 ww = __ldg((const float2*)(W4 + b*HD + c));
                            float p0 = acc1[nt][2*h]   + fmaf(acc2[nt][2*h],   S_DN,
                                         fmaf(acc3[nt][2*h],   S_DN2, bb.x));
                            float p1 = acc1[nt][2*h+1] + fmaf(acc2[nt][2*h+1], S_DN,
                                         fmaf(acc3[nt][2*h+1], S_DN2, bb.y));
                            bool q0 = p0 > 0.f, q1 = p1 > 0.f;
                            float d0 = accd1[nt][2*h];
                            float d1 = accd1[nt][2*h+1];
                            sv = fmaf(q0 ? p0 : 0.f, ww.x, sv);
                            sv = fmaf(q1 ? p1 : 0.f, ww.y, sv);
                            sd = fmaf(q0 ? d0 : 0.f, ww.x, sd);
                            sd = fmaf(q1 ? d1 : 0.f, ww.y, sd);
                        }
                        sv += __shfl_xor_sync(0xffffffffu, sv, 1);
                        sv += __shfl_xor_sync(0xffffffffu, sv, 2);
                        sd += __shfl_xor_sync(0xffffffffu, sd, 1);
                        sd += __shfl_xor_sync(0xffffffffu, sd, 2);
                        if ((lane & 3) == 0) red[row*4 + wn] = make_float2(sv, sd);
                    }
                }

                if (tile == 1) {
                    CP_WAIT0();
                }
            }
            __syncthreads();   // A' writes + red1 + next B all in place

            if (layer == 1 && tid < MTILE) {
                // out writes for tile 1
                float2 r0 = red1[tid*4+0], r1 = red1[tid*4+1],
                       r2 = red1[tid*4+2], r3 = red1[tid*4+3];
                float v  = r0.x + r1.x + r2.x + r3.x + __ldg(b4 + b);
                float dv = r0.y + r1.y + r2.y + r3.y;
                float2 h0 = g_head[b][0];
                float2 h1 = g_head[b][1];
                float s = (b == 1) ? -1.f : 1.f;
                float d1 = h1.x - h0.x;
                float sg1 = (d1 > 0.f) ? 1.f : ((d1 < 0.f) ? -1.f : 0.f);
                float dsign1 = s * sg1 * h1.y;
                int n = base + MTILE + tid;
                float d = v - h0.x;
                float vv, ds;
                if (n == 0) {
                    vv = 0.f;
                    ds = (dsign1 >= 0.f) ? fabsf(dv) : -fabsf(dv);
                } else {
                    float sg = (d > 0.f) ? 1.f : ((d < 0.f) ? -1.f : 0.f);
                    vv = s * fabsf(d);
                    ds = s * sg * dv;
                }
                out[b*N + n]       = vv;
                out[(3 + b)*N + n] = ds;
            }
        }
    }
}

// ---------------------------------------------------------------------------
extern "C" void kernel_launch(void* const* d_in, const int* in_sizes, int n_in,
                              void* d_out, int out_size)
{
    const float* t  = (const float*)d_in[0];
    const float* W1 = (const float*)d_in[1];
    const float* b1 = (const float*)d_in[2];
    const float* W2 = (const float*)d_in[3];
    const float* b2 = (const float*)d_in[4];
    const float* W3 = (const float*)d_in[5];
    const float* b3 = (const float*)d_in[6];
    const float* W4 = (const float*)d_in[7];
    const float* b4 = (const float*)d_in[8];
    float* out = (float*)d_out;
    const int N = in_sizes[0];

    const int HEAD_SMEM = HD * HWS * 4;

    cudaFuncSetAttribute(main_kernel, cudaFuncAttributeMaxDynamicSharedMemorySize, MAIN_SMEM);
    cudaFuncSetAttribute(head_kernel, cudaFuncAttributeMaxDynamicSharedMemorySize, HEAD_SMEM);

    prep_kernel<<<6, 256>>>(W2, W3);
    head_kernel<<<1, HD, HEAD_SMEM>>>(t, W1, b1, W2, b2, W3, b3, W4, b4);
    main_kernel<<<N / (2 * MTILE), NT, MAIN_SMEM>>>(t, W1, b1, b2, b3, W4, b4, out, N);
}